// round 13
// baseline (speedup 1.0000x reference)
#include <cuda_runtime.h>
#include <cuda_fp16.h>
#include <cstdint>

#define HW 65536

__device__ float g_xn[HW * 256];
__device__ float g_x1[HW * 256];
__device__ float g_bias[2 * 2 * 64 * 64];
__device__ uint32_t g_hh[512 * 32 * 2048];  // H fp16 frags [tblk][kc][2048 u32]
__device__ uint2 g_w1h[65536];              // W1 fp16 frag chunks [jb*8+kc][2048]
__device__ uint2 g_w2h[65536];              // W2 fp16 frag chunks [kc][2048]
__device__ uint2 g_wqkvh[24576];            // Wqkv fp16 frags [br][nb][kc][1024]
__device__ uint2 g_wph[8192];               // Wproj fp16 frags [br][kc][1024]

__device__ __forceinline__ uint32_t smem_u32(const void* p) {
    uint32_t a;
    asm("{ .reg .u64 t; cvta.to.shared.u64 t, %1; cvt.u32.u64 %0, t; }" : "=r"(a) : "l"(p));
    return a;
}
__device__ __forceinline__ void cp16(uint32_t dst, const void* src) {
    asm volatile("cp.async.cg.shared.global [%0], [%1], 16;" :: "r"(dst), "l"(src));
}
#define CP_COMMIT() asm volatile("cp.async.commit_group;" ::: "memory")
#define CP_WAIT2()  asm volatile("cp.async.wait_group 2;" ::: "memory")
#define CP_WAIT1()  asm volatile("cp.async.wait_group 1;" ::: "memory")
#define CP_WAIT0()  asm volatile("cp.async.wait_group 0;" ::: "memory")

__device__ __forceinline__ void mma16(float* d, const uint32_t* a, const uint32_t* b) {
    asm volatile("mma.sync.aligned.m16n8k16.row.col.f32.f16.f16.f32 "
        "{%0,%1,%2,%3}, {%4,%5,%6,%7}, {%8,%9}, {%0,%1,%2,%3};"
        : "+f"(d[0]), "+f"(d[1]), "+f"(d[2]), "+f"(d[3])
        : "r"(a[0]), "r"(a[1]), "r"(a[2]), "r"(a[3]), "r"(b[0]), "r"(b[1]));
}
__device__ __forceinline__ uint32_t packh2(float lo, float hi) {
    __half2 h = __floats2half2_rn(lo, hi);
    return *(uint32_t*)&h;
}
__device__ __forceinline__ float gelu(float v) {
    return 0.5f * v * (1.f + erff(v * 0.70710678118f));
}
// fp16 A-fragment half-index (verified): element (tok, k=c)
__device__ __forceinline__ int a16h(int tok, int c) {
    return ((((c >> 4) * 8 + (tok >> 4)) * 32 + ((c & 7) >> 1) * 8 + (tok & 7)) * 4
            + ((tok >> 3) & 1) + 2 * ((c >> 3) & 1)) * 2 + (c & 1);
}
// fp16 B-fragment half-index, N=128 region of k32 chunks (verified)
__device__ __forceinline__ int bfh(int k, int n) {
    return (k >> 5) * 4096
         + (((((k >> 4) & 1) * 16 + (n >> 3)) * 4 + ((k & 7) >> 1)) * 8 + (n & 7)) * 4
         + ((k >> 3) & 1) * 2 + (k & 1);
}

// ---------------- LN1 ----------------
__global__ void __launch_bounds__(256) ln1_kernel(const float* __restrict__ x,
                                                  const float* __restrict__ g,
                                                  const float* __restrict__ b) {
    __shared__ float s[256][33];
    __shared__ float mu[32], rs[32];
    int t0 = blockIdx.x * 32;
    int tid = threadIdx.x, lane = tid & 31, wid = tid >> 5;
    #pragma unroll
    for (int c = wid; c < 256; c += 8) s[c][lane] = x[c * HW + t0 + lane];
    __syncthreads();
    for (int it = 0; it < 4; it++) {
        int tok = wid * 4 + it;
        float sum = 0.f, sq = 0.f;
        #pragma unroll
        for (int j = 0; j < 8; j++) { float v = s[lane + 32 * j][tok]; sum += v; sq += v * v; }
        #pragma unroll
        for (int o = 16; o; o >>= 1) { sum += __shfl_down_sync(~0u, sum, o); sq += __shfl_down_sync(~0u, sq, o); }
        if (lane == 0) {
            float m = sum * (1.f / 256.f);
            mu[tok] = m; rs[tok] = rsqrtf(sq * (1.f / 256.f) - m * m + 1e-5f);
        }
    }
    __syncthreads();
    float gc = g[tid], bc = b[tid];
    for (int k = 0; k < 32; k++)
        g_xn[(t0 + k) * 256 + tid] = (s[tid][k] - mu[k]) * rs[k] * gc + bc;
}

// ---------------- bias tables ----------------
__global__ void bias_kernel(const float* __restrict__ tr, const float* __restrict__ ta) {
    for (int idx = threadIdx.x; idx < 16384; idx += blockDim.x) {
        int br = idx >> 13, rem = idx & 8191;
        int h = rem >> 12, n = (rem >> 6) & 63, m = rem & 63;
        int Wh = br ? 4 : 16, Ww = br ? 16 : 4, lg = br ? 4 : 2;
        int ridx = ((n >> lg) - (m >> lg) + Wh - 1) * (2 * Ww - 1) + ((n & (Ww - 1)) - (m & (Ww - 1)) + Ww - 1);
        g_bias[idx] = (br ? ta : tr)[ridx * 2 + h];
    }
}

// ---------------- MLP weight pre-format (fp16 frag order, verified) ----------------
__global__ void __launch_bounds__(256) wfmt_kernel(const float* __restrict__ W1,
                                                   const float* __restrict__ W2) {
    int idx = blockIdx.x * 256 + threadIdx.x;      // 0..131071
    const float* W; int ld, col, kbase; uint2* dst; int out;
    if (idx < 65536) {
        int g = idx & 7, tg = (idx >> 3) & 3, nt = (idx >> 5) & 31;
        int kb2 = (idx >> 10) & 1, kc = (idx >> 11) & 7, jb = idx >> 14;
        W = W1; ld = 1024;
        col = jb * 256 + nt * 8 + g;
        kbase = kc * 32 + kb2 * 16 + 2 * tg;
        out = (jb * 8 + kc) * 2048 + ((kb2 * 32 + nt) * 4 + tg) * 8 + g;
        dst = g_w1h;
    } else {
        int u = idx - 65536;
        int g = u & 7, tg = (u >> 3) & 3, nt = (u >> 5) & 31;
        int kb2 = (u >> 10) & 1, kc = u >> 11;
        W = W2; ld = 256;
        col = nt * 8 + g;
        kbase = kc * 32 + kb2 * 16 + 2 * tg;
        out = kc * 2048 + ((kb2 * 32 + nt) * 4 + tg) * 8 + g;
        dst = g_w2h;
    }
    float w0 = W[(size_t)kbase * ld + col];
    float w1 = W[(size_t)(kbase + 1) * ld + col];
    float w2 = W[(size_t)(kbase + 8) * ld + col];
    float w3 = W[(size_t)(kbase + 9) * ld + col];
    dst[out] = make_uint2(packh2(w0, w1), packh2(w2, w3));
}

// ---------------- attention weight pre-format (fp16 frags) ----------------
__global__ void __launch_bounds__(256) wfmt2h_kernel(
    const float* __restrict__ Wq_r, const float* __restrict__ Wp_r,
    const float* __restrict__ Wq_a, const float* __restrict__ Wp_a)
{
    int idx = blockIdx.x * 256 + threadIdx.x;      // 0..32767 (uint2 units)
    int i = idx & 1023;
    int g = i & 7, tg = (i >> 3) & 3, nt = (i >> 5) & 15, kb2 = i >> 9;
    const float* W; int ld, col, kc; uint2* dst; int out;
    if (idx < 24576) {
        int br = idx / 12288, r = idx % 12288;
        int nb = r >> 12; kc = (r >> 10) & 3;
        W = br ? Wq_a : Wq_r; ld = 384;
        col = nb * 128 + nt * 8 + g;
        dst = g_wqkvh; out = idx;
    } else {
        int j = idx - 24576;
        int br = j >> 12; kc = (j >> 10) & 3;
        W = br ? Wp_a : Wp_r; ld = 128;
        col = nt * 8 + g;
        dst = g_wph; out = j;
    }
    int kbase = kc * 32 + kb2 * 16 + 2 * tg;
    float w0 = W[(size_t)kbase * ld + col];
    float w1 = W[(size_t)(kbase + 1) * ld + col];
    float w2 = W[(size_t)(kbase + 8) * ld + col];
    float w3 = W[(size_t)(kbase + 9) * ld + col];
    dst[out] = make_uint2(packh2(w0, w1), packh2(w2, w3));
}

// ===========================================================================
// fp16 tensor-core window attention (unchanged from R12). 2 CTA/SM.
// ===========================================================================
#define ATTN_SMEM 114688
__device__ __forceinline__ int tok_t(int pair, int n, int lg, int nWb, int Wh, int Ww) {
    int w = n >> 6, nl = n & 63;
    int wi = pair * 2 + w;
    int hb = wi / nWb, wb = wi - hb * nWb;
    return ((hb * Wh + (nl >> lg)) << 8) + wb * Ww + (nl & (Ww - 1));
}

__global__ void __launch_bounds__(256, 2) attn_kernel(
    const float* __restrict__ bp_r, const float* __restrict__ bp_a)
{
    extern __shared__ float sm[];
    __half*  AXh = (__half*)sm;
    __half*  QAh = (__half*)((char*)sm + 32768);
    __half*  KBh = (__half*)((char*)sm + 65536);
    uint32_t bb_addr = smem_u32(sm) + 98304;
    float* red_max = (float*)KBh;
    float* red_sum = (float*)KBh + 512;

    int br = blockIdx.y;
    int co = br ? 128 : 0, lg = br ? 4 : 2;
    int Ww = 1 << lg, nWb = br ? 16 : 64, Wh = br ? 4 : 16;
    const float* bp = br ? bp_a : bp_r;
    int pair = blockIdx.x;
    int tid = threadIdx.x, wid = tid >> 5, lane = tid & 31;
    int g = lane >> 2, tg = lane & 3;

    {
        int k = tid & 127;
        #pragma unroll 2
        for (int it = 0; it < 64; it++) {
            int idx = it * 256 + tid;
            int n = idx >> 7;
            int t = tok_t(pair, n, lg, nWb, Wh, Ww);
            QAh[k * 130 + n] = __float2half_rn(g_xn[t * 256 + co + k]);
        }
    }
    __syncthreads();
    {
        uint4* AXu4 = (uint4*)AXh;
        #pragma unroll
        for (int i = 0; i < 8; i++) {
            int p = wid * 8 + i;
            int kb = p >> 3, mt = p & 7;
            int c0 = kb * 16 + 2 * tg, row = mt * 16 + g;
            uint4 u;
            u.x = packh2(__half2float(QAh[c0 * 130 + row]),       __half2float(QAh[(c0 + 1) * 130 + row]));
            u.y = packh2(__half2float(QAh[c0 * 130 + row + 8]),   __half2float(QAh[(c0 + 1) * 130 + row + 8]));
            u.z = packh2(__half2float(QAh[(c0 + 8) * 130 + row]), __half2float(QAh[(c0 + 9) * 130 + row]));
            u.w = packh2(__half2float(QAh[(c0 + 8) * 130 + row + 8]), __half2float(QAh[(c0 + 9) * 130 + row + 8]));
            AXu4[(kb * 8 + mt) * 32 + tg * 8 + g] = u;
        }
    }
    __syncthreads();

    int mwarp = wid >> 2, nwarp = wid & 3;
    float d[4][4][4];
    #pragma unroll
    for (int mt = 0; mt < 4; mt++)
        #pragma unroll
        for (int nt = 0; nt < 4; nt++)
            #pragma unroll
            for (int q = 0; q < 4; q++) d[mt][nt][q] = 0.f;

    const uint4* wsrc = (const uint4*)(g_wqkvh + (size_t)(br * 12) * 1024);
    {
        #pragma unroll
        for (int i = 0; i < 2; i++) cp16(bb_addr + (i * 256 + tid) * 16, wsrc + i * 256 + tid);
        CP_COMMIT();
    }
    for (int s = 0; s < 12; s++) {
        if (s < 11) {
            const uint4* s4 = wsrc + (s + 1) * 512;
            uint32_t db = bb_addr + ((s + 1) & 1) * 8192;
            #pragma unroll
            for (int i = 0; i < 2; i++) cp16(db + (i * 256 + tid) * 16, s4 + i * 256 + tid);
            CP_COMMIT();
            CP_WAIT1();
        } else CP_WAIT0();
        __syncthreads();
        int kc = s & 3;
        const uint2* Bu = (const uint2*)((char*)sm + 98304 + (s & 1) * 8192);
        const uint4* Au = (const uint4*)AXh;
        #pragma unroll
        for (int kb2 = 0; kb2 < 2; kb2++) {
            uint32_t a[4][4], b[4][2];
            #pragma unroll
            for (int mt = 0; mt < 4; mt++)
                *(uint4*)a[mt] = Au[((kc * 2 + kb2) * 8 + mwarp * 4 + mt) * 32 + tg * 8 + g];
            #pragma unroll
            for (int nt = 0; nt < 4; nt++)
                *(uint2*)b[nt] = Bu[((kb2 * 16 + nwarp * 4 + nt) * 4 + tg) * 8 + g];
            #pragma unroll
            for (int mt = 0; mt < 4; mt++)
                #pragma unroll
                for (int nt = 0; nt < 4; nt++)
                    mma16(d[mt][nt], a[mt], b[nt]);
        }
        __syncthreads();
        if (kc == 3) {
            int nb = s >> 2;
            uint32_t* Qw = (uint32_t*)QAh;
            uint32_t* Kw = (uint32_t*)KBh;
            #pragma unroll
            for (int mt = 0; mt < 4; mt++) {
                #pragma unroll
                for (int nt = 0; nt < 4; nt++) {
                    int row = mwarp * 64 + mt * 16 + g;
                    int col0 = nwarp * 32 + nt * 8 + 2 * tg;
                    if (nb == 0) {
                        Qw[a16h(row, col0) >> 1]     = packh2(d[mt][nt][0], d[mt][nt][1]);
                        Qw[a16h(row + 8, col0) >> 1] = packh2(d[mt][nt][2], d[mt][nt][3]);
                    } else if (nb == 1) {
                        Kw[bfh(col0, row) >> 1]      = packh2(d[mt][nt][0], d[mt][nt][1]);
                        Kw[bfh(col0, row + 8) >> 1]  = packh2(d[mt][nt][2], d[mt][nt][3]);
                    } else {
                        AXh[bfh(row, col0)]         = __float2half_rn(d[mt][nt][0]);
                        AXh[bfh(row, col0 + 1)]     = __float2half_rn(d[mt][nt][1]);
                        AXh[bfh(row + 8, col0)]     = __float2half_rn(d[mt][nt][2]);
                        AXh[bfh(row + 8, col0 + 1)] = __float2half_rn(d[mt][nt][3]);
                    }
                    #pragma unroll
                    for (int q = 0; q < 4; q++) d[mt][nt][q] = 0.f;
                }
            }
            __syncthreads();
        }
    }

    int w = wid >> 2, h = (wid >> 1) & 1, half = wid & 1;
    {
        const uint4* Qa = (const uint4*)QAh;
        const uint2* Kb = (const uint2*)KBh;
        #pragma unroll
        for (int kbl = 0; kbl < 4; kbl++) {
            uint32_t a[4][4], b[4][2];
            #pragma unroll
            for (int mt = 0; mt < 4; mt++)
                *(uint4*)a[mt] = Qa[((h * 4 + kbl) * 8 + w * 4 + mt) * 32 + tg * 8 + g];
            int kc2 = h * 2 + (kbl >> 1), kb2 = kbl & 1;
            #pragma unroll
            for (int nt = 0; nt < 4; nt++)
                *(uint2*)b[nt] = Kb[kc2 * 1024 + ((kb2 * 16 + w * 8 + half * 4 + nt) * 4 + tg) * 8 + g];
            #pragma unroll
            for (int mt = 0; mt < 4; mt++)
                #pragma unroll
                for (int nt = 0; nt < 4; nt++)
                    mma16(d[mt][nt], a[mt], b[nt]);
        }
    }
    __syncthreads();

    const float* bias = g_bias + (br * 2 + h) * 4096;
    #pragma unroll
    for (int mt = 0; mt < 4; mt++) {
        #pragma unroll
        for (int nt = 0; nt < 4; nt++) {
            int rr = mt * 16 + g, cc = half * 32 + nt * 8 + 2 * tg;
            float2 b0 = *(const float2*)(bias + rr * 64 + cc);
            float2 b1 = *(const float2*)(bias + (rr + 8) * 64 + cc);
            d[mt][nt][0] = d[mt][nt][0] * 0.125f + b0.x;
            d[mt][nt][1] = d[mt][nt][1] * 0.125f + b0.y;
            d[mt][nt][2] = d[mt][nt][2] * 0.125f + b1.x;
            d[mt][nt][3] = d[mt][nt][3] * 0.125f + b1.y;
        }
    }
    int whb = ((w * 2 + h) * 2 + half) * 64;
    #pragma unroll
    for (int mt = 0; mt < 4; mt++) {
        float m0 = -1e30f, m1 = -1e30f;
        #pragma unroll
        for (int nt = 0; nt < 4; nt++) {
            m0 = fmaxf(m0, fmaxf(d[mt][nt][0], d[mt][nt][1]));
            m1 = fmaxf(m1, fmaxf(d[mt][nt][2], d[mt][nt][3]));
        }
        m0 = fmaxf(m0, __shfl_xor_sync(~0u, m0, 1)); m0 = fmaxf(m0, __shfl_xor_sync(~0u, m0, 2));
        m1 = fmaxf(m1, __shfl_xor_sync(~0u, m1, 1)); m1 = fmaxf(m1, __shfl_xor_sync(~0u, m1, 2));
        red_max[whb + mt * 16 + g] = m0;
        red_max[whb + mt * 16 + g + 8] = m1;
    }
    __syncthreads();
    int whb0 = ((w * 2 + h) * 2) * 64;
    #pragma unroll
    for (int mt = 0; mt < 4; mt++) {
        float M0 = fmaxf(red_max[whb0 + mt * 16 + g], red_max[whb0 + 64 + mt * 16 + g]);
        float M1 = fmaxf(red_max[whb0 + mt * 16 + g + 8], red_max[whb0 + 64 + mt * 16 + g + 8]);
        float s0 = 0.f, s1 = 0.f;
        #pragma unroll
        for (int nt = 0; nt < 4; nt++) {
            d[mt][nt][0] = expf(d[mt][nt][0] - M0); s0 += d[mt][nt][0];
            d[mt][nt][1] = expf(d[mt][nt][1] - M0); s0 += d[mt][nt][1];
            d[mt][nt][2] = expf(d[mt][nt][2] - M1); s1 += d[mt][nt][2];
            d[mt][nt][3] = expf(d[mt][nt][3] - M1); s1 += d[mt][nt][3];
        }
        s0 += __shfl_xor_sync(~0u, s0, 1); s0 += __shfl_xor_sync(~0u, s0, 2);
        s1 += __shfl_xor_sync(~0u, s1, 1); s1 += __shfl_xor_sync(~0u, s1, 2);
        red_sum[whb + mt * 16 + g] = s0;
        red_sum[whb + mt * 16 + g + 8] = s1;
    }
    __syncthreads();
    {
        uint32_t* Pw = (uint32_t*)QAh;
        #pragma unroll
        for (int mt = 0; mt < 4; mt++) {
            float i0 = 1.f / (red_sum[whb0 + mt * 16 + g] + red_sum[whb0 + 64 + mt * 16 + g]);
            float i1 = 1.f / (red_sum[whb0 + mt * 16 + g + 8] + red_sum[whb0 + 64 + mt * 16 + g + 8]);
            #pragma unroll
            for (int nt = 0; nt < 4; nt++) {
                int row = w * 64 + mt * 16 + g;
                int m0 = half * 32 + nt * 8 + 2 * tg;
                Pw[a16h(row, h * 64 + m0) >> 1]     = packh2(d[mt][nt][0] * i0, d[mt][nt][1] * i0);
                Pw[a16h(row + 8, h * 64 + m0) >> 1] = packh2(d[mt][nt][2] * i1, d[mt][nt][3] * i1);
                #pragma unroll
                for (int q = 0; q < 4; q++) d[mt][nt][q] = 0.f;
            }
        }
    }
    __syncthreads();

    {
        const uint4* Pa = (const uint4*)QAh;
        const uint2* Vb = (const uint2*)AXh;
        #pragma unroll
        for (int kbl = 0; kbl < 4; kbl++) {
            uint32_t a[4][4], b[4][2];
            #pragma unroll
            for (int mt = 0; mt < 4; mt++)
                *(uint4*)a[mt] = Pa[((h * 4 + kbl) * 8 + w * 4 + mt) * 32 + tg * 8 + g];
            int kc2 = w * 2 + (kbl >> 1), kb2 = kbl & 1;
            #pragma unroll
            for (int nt = 0; nt < 4; nt++)
                *(uint2*)b[nt] = Vb[kc2 * 1024 + ((kb2 * 16 + h * 8 + half * 4 + nt) * 4 + tg) * 8 + g];
            #pragma unroll
            for (int mt = 0; mt < 4; mt++)
                #pragma unroll
                for (int nt = 0; nt < 4; nt++)
                    mma16(d[mt][nt], a[mt], b[nt]);
        }
    }
    __syncthreads();
    {
        uint32_t* Ow = (uint32_t*)KBh;
        #pragma unroll
        for (int mt = 0; mt < 4; mt++) {
            #pragma unroll
            for (int nt = 0; nt < 4; nt++) {
                int row = w * 64 + mt * 16 + g;
                int col0 = h * 64 + half * 32 + nt * 8 + 2 * tg;
                Ow[a16h(row, col0) >> 1]     = packh2(d[mt][nt][0], d[mt][nt][1]);
                Ow[a16h(row + 8, col0) >> 1] = packh2(d[mt][nt][2], d[mt][nt][3]);
                #pragma unroll
                for (int q = 0; q < 4; q++) d[mt][nt][q] = 0.f;
            }
        }
    }
    __syncthreads();

    const uint4* psrc = (const uint4*)(g_wph + (size_t)(br * 4) * 1024);
    {
        #pragma unroll
        for (int i = 0; i < 2; i++) cp16(bb_addr + (i * 256 + tid) * 16, psrc + i * 256 + tid);
        CP_COMMIT();
    }
    for (int kc = 0; kc < 4; kc++) {
        if (kc < 3) {
            const uint4* s4 = psrc + (kc + 1) * 512;
            uint32_t db = bb_addr + ((kc + 1) & 1) * 8192;
            #pragma unroll
            for (int i = 0; i < 2; i++) cp16(db + (i * 256 + tid) * 16, s4 + i * 256 + tid);
            CP_COMMIT();
            CP_WAIT1();
        } else CP_WAIT0();
        __syncthreads();
        const uint2* Bu = (const uint2*)((char*)sm + 98304 + (kc & 1) * 8192);
        const uint4* Au = (const uint4*)KBh;
        #pragma unroll
        for (int kb2 = 0; kb2 < 2; kb2++) {
            uint32_t a[4][4], b[4][2];
            #pragma unroll
            for (int mt = 0; mt < 4; mt++)
                *(uint4*)a[mt] = Au[((kc * 2 + kb2) * 8 + mwarp * 4 + mt) * 32 + tg * 8 + g];
            #pragma unroll
            for (int nt = 0; nt < 4; nt++)
                *(uint2*)b[nt] = Bu[((kb2 * 16 + nwarp * 4 + nt) * 4 + tg) * 8 + g];
            #pragma unroll
            for (int mt = 0; mt < 4; mt++)
                #pragma unroll
                for (int nt = 0; nt < 4; nt++)
                    mma16(d[mt][nt], a[mt], b[nt]);
        }
        __syncthreads();
    }

    float* Sf = (float*)AXh;
    for (int p = 0; p < 2; p++) {
        __syncthreads();
        if (mwarp == p) {
            #pragma unroll
            for (int mt = 0; mt < 4; mt++) {
                #pragma unroll
                for (int nt = 0; nt < 4; nt++) {
                    #pragma unroll
                    for (int q = 0; q < 4; q++) {
                        int row = mt * 16 + g + (q >> 1) * 8;
                        int col = nwarp * 32 + nt * 8 + 2 * tg + (q & 1);
                        Sf[row * 132 + col] = d[mt][nt][q] + bp[col];
                    }
                }
            }
        }
        __syncthreads();
        int c = tid & 127;
        #pragma unroll
        for (int it = 0; it < 32; it++) {
            int idx = it * 256 + tid;
            int nl = idx >> 7;
            int n = p * 64 + nl;
            int t = tok_t(pair, n, lg, nWb, Wh, Ww);
            g_x1[t * 256 + co + c] = Sf[nl * 132 + c] + g_xn[t * 256 + co + c];
        }
    }
}

// ===========================================================================
// MLP1 (fp16, 512 thr / 16 warps, warp tile 32x64): LN2 + GEMM1 + GELU -> g_hh
// smem bytes: A halves 65536 @0 | B ring 3x16384 @65536 (LN overlay inside ring)
// ===========================================================================
#define M1_SMEM 114688
__global__ void __launch_bounds__(512, 1) mlp1_kernel(
    const float* __restrict__ x, const float* __restrict__ g2, const float* __restrict__ b2,
    const float* __restrict__ b1)
{
    extern __shared__ float sm[];
    __half* Ah   = (__half*)sm;          // 32768 halves (64KB)
    float* S32   = sm + 16384;           // [32][129] floats, overlay on B ring
    float* tmpS  = sm + 16384 + 4160;    // 512
    float* tmpQ  = tmpS + 512;           // 512
    float* mu    = tmpQ + 512;           // 128
    float* rs    = mu + 128;             // 128

    int tid = threadIdx.x, wid = tid >> 5, lane = tid & 31;
    int t0 = blockIdx.x * 128;
    int tblk = blockIdx.x;
    uint32_t bbase = smem_u32(sm) + 65536;

    // ---- LN2: stats + raw fp16 stash, 8 channel-blocks of 32 ----
    float accS = 0.f, accQ = 0.f;
    int nrole = tid & 127, part = tid >> 7;   // part 0..3
    for (int cb = 0; cb < 8; cb++) {
        __syncthreads();
        #pragma unroll
        for (int it = 0; it < 8; it++) {
            int idx = it * 512 + tid;
            int n = idx & 127, cl = idx >> 7;
            S32[cl * 129 + n] = x[(size_t)(cb * 32 + cl) * HW + t0 + n];
        }
        __syncthreads();
        #pragma unroll
        for (int it = 0; it < 8; it++) {
            int idx = it * 512 + tid;
            int c = idx & 31, n = idx >> 5;
            S32[c * 129 + n] += g_x1[(size_t)(t0 + n) * 256 + cb * 32 + c];
        }
        __syncthreads();
        #pragma unroll
        for (int i = 0; i < 8; i++) {
            int cl = part * 8 + i;
            float v = S32[cl * 129 + nrole];
            accS += v; accQ += v * v;
            Ah[a16h(nrole, cb * 32 + cl)] = __float2half_rn(v);
        }
    }
    __syncthreads();
    tmpS[part * 128 + nrole] = accS;
    tmpQ[part * 128 + nrole] = accQ;
    __syncthreads();
    if (tid < 128) {
        float s1 = tmpS[tid] + tmpS[128 + tid] + tmpS[256 + tid] + tmpS[384 + tid];
        float s2 = tmpQ[tid] + tmpQ[128 + tid] + tmpQ[256 + tid] + tmpQ[384 + tid];
        float m = s1 * (1.f / 256.f);
        mu[tid] = m;
        rs[tid] = rsqrtf(s2 * (1.f / 256.f) - m * m + 1e-5f);
    }
    __syncthreads();
    {
        int tok = tid & 127, qr = tid >> 7;   // 0..3, 64 channels each
        float m = mu[tok], r = rs[tok];
        for (int c = qr * 64; c < qr * 64 + 64; c++) {
            int hi = a16h(tok, c);
            float v = __half2float(Ah[hi]);
            Ah[hi] = __float2half_rn((v - m) * r * __ldg(g2 + c) + __ldg(b2 + c));
        }
    }
    __syncthreads();

    // ---- GEMM1 (fp16), 16 warps: 4m x 4n, warp tile 32 tok x 64 col ----
    int mwarp = wid >> 2, nwarp = wid & 3;
    int g = lane >> 2, tg = lane & 3;
    const uint4* Au = (const uint4*)Ah;

    for (int jb = 0; jb < 4; jb++) {
        float d[2][8][4];
        #pragma unroll
        for (int mt = 0; mt < 2; mt++)
            #pragma unroll
            for (int nt = 0; nt < 8; nt++)
                #pragma unroll
                for (int q = 0; q < 4; q++) d[mt][nt][q] = 0.f;

        {
            const uint4* src = (const uint4*)g_w1h + (size_t)(jb * 8) * 1024;
            #pragma unroll
            for (int i = 0; i < 2; i++) cp16(bbase + (i * 512 + tid) * 16, src + i * 512 + tid);
            CP_COMMIT();
        }
        for (int kc = 0; kc < 8; kc++) {
            if (kc + 1 < 8) {
                const uint4* src = (const uint4*)g_w1h + (size_t)(jb * 8 + kc + 1) * 1024;
                uint32_t db = bbase + (uint32_t)(((kc + 1) % 3) * 16384);
                #pragma unroll
                for (int i = 0; i < 2; i++) cp16(db + (i * 512 + tid) * 16, src + i * 512 + tid);
            }
            CP_COMMIT();
            CP_WAIT1();
            __syncthreads();
            const uint2* Bu = (const uint2*)((char*)sm + 65536 + (kc % 3) * 16384);
            #pragma unroll
            for (int kb2 = 0; kb2 < 2; kb2++) {
                uint32_t a[2][4], b[8][2];
                #pragma unroll
                for (int mt = 0; mt < 2; mt++)
                    *(uint4*)a[mt] = Au[((kc * 2 + kb2) * 8 + mwarp * 2 + mt) * 32 + tg * 8 + g];
                #pragma unroll
                for (int nt = 0; nt < 8; nt++)
                    *(uint2*)b[nt] = Bu[((kb2 * 32 + nwarp * 8 + nt) * 4 + tg) * 8 + g];
                #pragma unroll
                for (int mt = 0; mt < 2; mt++)
                    #pragma unroll
                    for (int nt = 0; nt < 8; nt++)
                        mma16(d[mt][nt], a[mt], b[nt]);
            }
        }
        __syncthreads();
        // epilogue: bias + GELU -> g_hh fp16 frags
        #pragma unroll
        for (int mt = 0; mt < 2; mt++) {
            #pragma unroll
            for (int nt = 0; nt < 8; nt++) {
                int row0 = mwarp * 32 + mt * 16 + g;
                int col0 = jb * 256 + nwarp * 64 + nt * 8 + 2 * tg;
                float b0v = b1[col0], b1v = b1[col0 + 1];
                float v0 = gelu(d[mt][nt][0] + b0v);
                float v1 = gelu(d[mt][nt][1] + b1v);
                float v2 = gelu(d[mt][nt][2] + b0v);
                float v3 = gelu(d[mt][nt][3] + b1v);
                int chunk = tblk * 32 + (col0 >> 5);
                int slotu = (((col0 >> 4) & 1) * 8 + mwarp * 2 + mt) * 32 + tg * 8 + g;
                int base = chunk * 2048 + slotu * 4 + 2 * (nt & 1);
                g_hh[base]     = packh2(v0, v1);
                g_hh[base + 1] = packh2(v2, v3);
            }
        }
    }
}

// ===========================================================================
// MLP2 (fp16, 512 thr / 16 warps, warp tile 32x64): GEMM2 + residual -> out
// smem bytes: A ring 4x8192 @0 | B ring 4x16384 @32768 | epi overlay S[256][69] @0
// ===========================================================================
#define M2_SMEM 98304
__global__ void __launch_bounds__(512, 1) mlp2_kernel(
    const float* __restrict__ x, const float* __restrict__ b2o, float* __restrict__ out)
{
    extern __shared__ float sm[];
    float* S = sm;

    int tid = threadIdx.x, wid = tid >> 5, lane = tid & 31;
    int t0 = blockIdx.x * 128;
    int tblk = blockIdx.x;
    int mwarp = wid >> 2, nwarp = wid & 3;
    int g = lane >> 2, tg = lane & 3;
    uint32_t abase = smem_u32(sm);
    uint32_t bbase = abase + 32768;

    float d[2][8][4];
    #pragma unroll
    for (int mt = 0; mt < 2; mt++)
        #pragma unroll
        for (int nt = 0; nt < 8; nt++)
            #pragma unroll
            for (int q = 0; q < 4; q++) d[mt][nt][q] = 0.f;

    #pragma unroll
    for (int p = 0; p < 2; p++) {
        const uint4* asrc = (const uint4*)g_hh + (size_t)(tblk * 32 + p) * 512;
        uint32_t da = abase + (uint32_t)(p * 8192);
        cp16(da + tid * 16, asrc + tid);
        const uint4* bsrc = (const uint4*)g_w2h + (size_t)p * 1024;
        uint32_t db = bbase + (uint32_t)(p * 16384);
        #pragma unroll
        for (int i = 0; i < 2; i++) cp16(db + (i * 512 + tid) * 16, bsrc + i * 512 + tid);
        CP_COMMIT();
    }
    for (int kc = 0; kc < 32; kc++) {
        if (kc + 2 < 32) {
            int nx = kc + 2, slot = nx & 3;
            const uint4* asrc = (const uint4*)g_hh + (size_t)(tblk * 32 + nx) * 512;
            uint32_t da = abase + (uint32_t)(slot * 8192);
            cp16(da + tid * 16, asrc + tid);
            const uint4* bsrc = (const uint4*)g_w2h + (size_t)nx * 1024;
            uint32_t db = bbase + (uint32_t)(slot * 16384);
            #pragma unroll
            for (int i = 0; i < 2; i++) cp16(db + (i * 512 + tid) * 16, bsrc + i * 512 + tid);
        }
        CP_COMMIT();
        CP_WAIT2();
        __syncthreads();
        const uint4* Au = (const uint4*)((char*)sm + (kc & 3) * 8192);
        const uint2* Bu = (const uint2*)((char*)sm + 32768 + (kc & 3) * 16384);
        #pragma unroll
        for (int kb2 = 0; kb2 < 2; kb2++) {
            uint32_t a[2][4], b[8][2];
            #pragma unroll
            for (int mt = 0; mt < 2; mt++)
                *(uint4*)a[mt] = Au[(kb2 * 8 + mwarp * 2 + mt) * 32 + tg * 8 + g];
            #pragma unroll
            for (int nt = 0; nt < 8; nt++)
                *(uint2*)b[nt] = Bu[((kb2 * 32 + nwarp * 8 + nt) * 4 + tg) * 8 + g];
            #pragma unroll
            for (int mt = 0; mt < 2; mt++)
                #pragma unroll
                for (int nt = 0; nt < 8; nt++)
                    mma16(d[mt][nt], a[mt], b[nt]);
        }
    }
    __syncthreads();

    // epilogue: 2 passes of 64 tokens; warps with mwarp>>1 == p write
    for (int p = 0; p < 2; p++) {
        __syncthreads();
        #pragma unroll 4
        for (int it = 0; it < 32; it++) {
            int idx = it * 512 + tid;
            int c = idx & 255, nl = idx >> 8;
            S[c * 69 + nl] = g_x1[(size_t)(t0 + p * 64 + nl) * 256 + c];
        }
        __syncthreads();
        if ((mwarp >> 1) == p) {
            #pragma unroll
            for (int mt = 0; mt < 2; mt++) {
                #pragma unroll
                for (int nt = 0; nt < 8; nt++) {
                    int row0 = mwarp * 32 + mt * 16 + g;
                    int col0 = nwarp * 64 + nt * 8 + 2 * tg;
                    #pragma unroll
                    for (int q = 0; q < 4; q++) {
                        int col = col0 + (q & 1);
                        int row = row0 + (q >> 1) * 8;
                        float v = d[mt][nt][q] + b2o[col]
                                + x[(size_t)col * HW + t0 + row] + S[col * 69 + (row - p * 64)];
                        out[(size_t)col * HW + t0 + row] = v;
                    }
                }
            }
        }
    }
}

// ---------------------------------------------------------------------------
extern "C" void kernel_launch(void* const* d_in, const int* in_sizes, int n_in,
                              void* d_out, int out_size) {
    const float* x        = (const float*)d_in[0];
    const float* norm1_g  = (const float*)d_in[1];
    const float* norm1_b  = (const float*)d_in[2];
    const float* qkv_r    = (const float*)d_in[3];
    const float* proj_r_w = (const float*)d_in[4];
    const float* proj_r_b = (const float*)d_in[5];
    const float* table_r  = (const float*)d_in[6];
    const float* qkv_a    = (const float*)d_in[7];
    const float* proj_a_w = (const float*)d_in[8];
    const float* proj_a_b = (const float*)d_in[9];
    const float* table_a  = (const float*)d_in[10];
    const float* norm2_g  = (const float*)d_in[11];
    const float* norm2_b  = (const float*)d_in[12];
    const float* mlp_w1   = (const float*)d_in[13];
    const float* mlp_b1   = (const float*)d_in[14];
    const float* mlp_w2   = (const float*)d_in[15];
    const float* mlp_b2   = (const float*)d_in[16];
    float* out = (float*)d_out;

    cudaFuncSetAttribute(attn_kernel, cudaFuncAttributeMaxDynamicSharedMemorySize, ATTN_SMEM);
    cudaFuncSetAttribute(mlp1_kernel, cudaFuncAttributeMaxDynamicSharedMemorySize, M1_SMEM);
    cudaFuncSetAttribute(mlp2_kernel, cudaFuncAttributeMaxDynamicSharedMemorySize, M2_SMEM);

    ln1_kernel<<<2048, 256>>>(x, norm1_g, norm1_b);
    bias_kernel<<<1, 256>>>(table_r, table_a);
    wfmt_kernel<<<512, 256>>>(mlp_w1, mlp_w2);
    wfmt2h_kernel<<<128, 256>>>(qkv_r, proj_r_w, qkv_a, proj_a_w);
    attn_kernel<<<dim3(512, 2), 256, ATTN_SMEM>>>(proj_r_b, proj_a_b);
    mlp1_kernel<<<512, 512, M1_SMEM>>>(x, norm2_g, norm2_b, mlp_b1);
    mlp2_kernel<<<512, 512, M2_SMEM>>>(x, mlp_b2, out);
}

// round 15
// speedup vs baseline: 1.0136x; 1.0136x over previous
#include <cuda_runtime.h>
#include <cuda_fp16.h>
#include <cstdint>

#define HW 65536

__device__ float g_xn[HW * 256];
__device__ float g_x1[HW * 256];
__device__ float g_bias[2 * 2 * 64 * 64];
__device__ uint2 g_w1h[65536];              // W1 fp16 frag chunks [hb*8+kc][1024] (k32 x n128)
__device__ uint2 g_w2h[65536];              // W2 fp16 frag chunks [kc][2048]      (k32 x n256)
__device__ uint2 g_wqkvh[24576];            // Wqkv fp16 frags [br][nb][kc][1024]
__device__ uint2 g_wph[8192];               // Wproj fp16 frags [br][kc][1024]

__device__ __forceinline__ uint32_t smem_u32(const void* p) {
    uint32_t a;
    asm("{ .reg .u64 t; cvta.to.shared.u64 t, %1; cvt.u32.u64 %0, t; }" : "=r"(a) : "l"(p));
    return a;
}
__device__ __forceinline__ void cp16(uint32_t dst, const void* src) {
    asm volatile("cp.async.cg.shared.global [%0], [%1], 16;" :: "r"(dst), "l"(src));
}
#define CP_COMMIT() asm volatile("cp.async.commit_group;" ::: "memory")
#define CP_WAIT1()  asm volatile("cp.async.wait_group 1;" ::: "memory")
#define CP_WAIT0()  asm volatile("cp.async.wait_group 0;" ::: "memory")

__device__ __forceinline__ void mma16(float* d, const uint32_t* a, const uint32_t* b) {
    asm volatile("mma.sync.aligned.m16n8k16.row.col.f32.f16.f16.f32 "
        "{%0,%1,%2,%3}, {%4,%5,%6,%7}, {%8,%9}, {%0,%1,%2,%3};"
        : "+f"(d[0]), "+f"(d[1]), "+f"(d[2]), "+f"(d[3])
        : "r"(a[0]), "r"(a[1]), "r"(a[2]), "r"(a[3]), "r"(b[0]), "r"(b[1]));
}
__device__ __forceinline__ uint32_t packh2(float lo, float hi) {
    __half2 h = __floats2half2_rn(lo, hi);
    return *(uint32_t*)&h;
}
__device__ __forceinline__ float gelu(float v) {
    return 0.5f * v * (1.f + erff(v * 0.70710678118f));
}
// fp16 A-fragment half-index (verified): element (tok, k=c)
__device__ __forceinline__ int a16h(int tok, int c) {
    return ((((c >> 4) * 8 + (tok >> 4)) * 32 + ((c & 7) >> 1) * 8 + (tok & 7)) * 4
            + ((tok >> 3) & 1) + 2 * ((c >> 3) & 1)) * 2 + (c & 1);
}
// fp16 B-fragment half-index, N=128 region of k32 chunks (verified)
__device__ __forceinline__ int bfh(int k, int n) {
    return (k >> 5) * 4096
         + (((((k >> 4) & 1) * 16 + (n >> 3)) * 4 + ((k & 7) >> 1)) * 8 + (n & 7)) * 4
         + ((k >> 3) & 1) * 2 + (k & 1);
}

// ---------------- LN1 ----------------
__global__ void __launch_bounds__(256) ln1_kernel(const float* __restrict__ x,
                                                  const float* __restrict__ g,
                                                  const float* __restrict__ b) {
    __shared__ float s[256][33];
    __shared__ float mu[32], rs[32];
    int t0 = blockIdx.x * 32;
    int tid = threadIdx.x, lane = tid & 31, wid = tid >> 5;
    #pragma unroll
    for (int c = wid; c < 256; c += 8) s[c][lane] = x[c * HW + t0 + lane];
    __syncthreads();
    for (int it = 0; it < 4; it++) {
        int tok = wid * 4 + it;
        float sum = 0.f, sq = 0.f;
        #pragma unroll
        for (int j = 0; j < 8; j++) { float v = s[lane + 32 * j][tok]; sum += v; sq += v * v; }
        #pragma unroll
        for (int o = 16; o; o >>= 1) { sum += __shfl_down_sync(~0u, sum, o); sq += __shfl_down_sync(~0u, sq, o); }
        if (lane == 0) {
            float m = sum * (1.f / 256.f);
            mu[tok] = m; rs[tok] = rsqrtf(sq * (1.f / 256.f) - m * m + 1e-5f);
        }
    }
    __syncthreads();
    float gc = g[tid], bc = b[tid];
    for (int k = 0; k < 32; k++)
        g_xn[(t0 + k) * 256 + tid] = (s[tid][k] - mu[k]) * rs[k] * gc + bc;
}

// ---------------- bias tables ----------------
__global__ void bias_kernel(const float* __restrict__ tr, const float* __restrict__ ta) {
    for (int idx = threadIdx.x; idx < 16384; idx += blockDim.x) {
        int br = idx >> 13, rem = idx & 8191;
        int h = rem >> 12, n = (rem >> 6) & 63, m = rem & 63;
        int Wh = br ? 4 : 16, Ww = br ? 16 : 4, lg = br ? 4 : 2;
        int ridx = ((n >> lg) - (m >> lg) + Wh - 1) * (2 * Ww - 1) + ((n & (Ww - 1)) - (m & (Ww - 1)) + Ww - 1);
        g_bias[idx] = (br ? ta : tr)[ridx * 2 + h];
    }
}

// ---------------- MLP weight pre-format ----------------
__global__ void __launch_bounds__(256) wfmt_kernel(const float* __restrict__ W1,
                                                   const float* __restrict__ W2) {
    int idx = blockIdx.x * 256 + threadIdx.x;      // 0..131071
    if (idx < 65536) {
        int i = idx & 1023;
        int g = i & 7, tg = (i >> 3) & 3, nt = (i >> 5) & 15, kb2 = i >> 9;
        int chunk = idx >> 10;                     // hb*8 + kc
        int hb = chunk >> 3, kc = chunk & 7;
        int col = hb * 128 + nt * 8 + g;
        int kbase = kc * 32 + kb2 * 16 + 2 * tg;
        float w0 = W1[(size_t)kbase * 1024 + col];
        float w1 = W1[(size_t)(kbase + 1) * 1024 + col];
        float w2 = W1[(size_t)(kbase + 8) * 1024 + col];
        float w3 = W1[(size_t)(kbase + 9) * 1024 + col];
        g_w1h[chunk * 1024 + ((kb2 * 16 + nt) * 4 + tg) * 8 + g]
            = make_uint2(packh2(w0, w1), packh2(w2, w3));
    } else {
        int u = idx - 65536;
        int g = u & 7, tg = (u >> 3) & 3, nt = (u >> 5) & 31;
        int kb2 = (u >> 10) & 1, kc = u >> 11;
        int col = nt * 8 + g;
        int kbase = kc * 32 + kb2 * 16 + 2 * tg;
        float w0 = W2[(size_t)kbase * 256 + col];
        float w1 = W2[(size_t)(kbase + 1) * 256 + col];
        float w2 = W2[(size_t)(kbase + 8) * 256 + col];
        float w3 = W2[(size_t)(kbase + 9) * 256 + col];
        g_w2h[kc * 2048 + ((kb2 * 32 + nt) * 4 + tg) * 8 + g]
            = make_uint2(packh2(w0, w1), packh2(w2, w3));
    }
}

// ---------------- attention weight pre-format (fp16 frags) ----------------
__global__ void __launch_bounds__(256) wfmt2h_kernel(
    const float* __restrict__ Wq_r, const float* __restrict__ Wp_r,
    const float* __restrict__ Wq_a, const float* __restrict__ Wp_a)
{
    int idx = blockIdx.x * 256 + threadIdx.x;      // 0..32767 (uint2 units)
    int i = idx & 1023;
    int g = i & 7, tg = (i >> 3) & 3, nt = (i >> 5) & 15, kb2 = i >> 9;
    const float* W; int ld, col, kc; uint2* dst; int out;
    if (idx < 24576) {
        int br = idx / 12288, r = idx % 12288;
        int nb = r >> 12; kc = (r >> 10) & 3;
        W = br ? Wq_a : Wq_r; ld = 384;
        col = nb * 128 + nt * 8 + g;
        dst = g_wqkvh; out = idx;
    } else {
        int j = idx - 24576;
        int br = j >> 12; kc = (j >> 10) & 3;
        W = br ? Wp_a : Wp_r; ld = 128;
        col = nt * 8 + g;
        dst = g_wph; out = j;
    }
    int kbase = kc * 32 + kb2 * 16 + 2 * tg;
    float w0 = W[(size_t)kbase * ld + col];
    float w1 = W[(size_t)(kbase + 1) * ld + col];
    float w2 = W[(size_t)(kbase + 8) * ld + col];
    float w3 = W[(size_t)(kbase + 9) * ld + col];
    dst[out] = make_uint2(packh2(w0, w1), packh2(w2, w3));
}

// ===========================================================================
// fp16 tensor-core window attention (unchanged from R12). 2 CTA/SM.
// ===========================================================================
#define ATTN_SMEM 114688
__device__ __forceinline__ int tok_t(int pair, int n, int lg, int nWb, int Wh, int Ww) {
    int w = n >> 6, nl = n & 63;
    int wi = pair * 2 + w;
    int hb = wi / nWb, wb = wi - hb * nWb;
    return ((hb * Wh + (nl >> lg)) << 8) + wb * Ww + (nl & (Ww - 1));
}

__global__ void __launch_bounds__(256, 2) attn_kernel(
    const float* __restrict__ bp_r, const float* __restrict__ bp_a)
{
    extern __shared__ float sm[];
    __half*  AXh = (__half*)sm;
    __half*  QAh = (__half*)((char*)sm + 32768);
    __half*  KBh = (__half*)((char*)sm + 65536);
    uint32_t bb_addr = smem_u32(sm) + 98304;
    float* red_max = (float*)KBh;
    float* red_sum = (float*)KBh + 512;

    int br = blockIdx.y;
    int co = br ? 128 : 0, lg = br ? 4 : 2;
    int Ww = 1 << lg, nWb = br ? 16 : 64, Wh = br ? 4 : 16;
    const float* bp = br ? bp_a : bp_r;
    int pair = blockIdx.x;
    int tid = threadIdx.x, wid = tid >> 5, lane = tid & 31;
    int g = lane >> 2, tg = lane & 3;

    {
        int k = tid & 127;
        #pragma unroll 2
        for (int it = 0; it < 64; it++) {
            int idx = it * 256 + tid;
            int n = idx >> 7;
            int t = tok_t(pair, n, lg, nWb, Wh, Ww);
            QAh[k * 130 + n] = __float2half_rn(g_xn[t * 256 + co + k]);
        }
    }
    __syncthreads();
    {
        uint4* AXu4 = (uint4*)AXh;
        #pragma unroll
        for (int i = 0; i < 8; i++) {
            int p = wid * 8 + i;
            int kb = p >> 3, mt = p & 7;
            int c0 = kb * 16 + 2 * tg, row = mt * 16 + g;
            uint4 u;
            u.x = packh2(__half2float(QAh[c0 * 130 + row]),       __half2float(QAh[(c0 + 1) * 130 + row]));
            u.y = packh2(__half2float(QAh[c0 * 130 + row + 8]),   __half2float(QAh[(c0 + 1) * 130 + row + 8]));
            u.z = packh2(__half2float(QAh[(c0 + 8) * 130 + row]), __half2float(QAh[(c0 + 9) * 130 + row]));
            u.w = packh2(__half2float(QAh[(c0 + 8) * 130 + row + 8]), __half2float(QAh[(c0 + 9) * 130 + row + 8]));
            AXu4[(kb * 8 + mt) * 32 + tg * 8 + g] = u;
        }
    }
    __syncthreads();

    int mwarp = wid >> 2, nwarp = wid & 3;
    float d[4][4][4];
    #pragma unroll
    for (int mt = 0; mt < 4; mt++)
        #pragma unroll
        for (int nt = 0; nt < 4; nt++)
            #pragma unroll
            for (int q = 0; q < 4; q++) d[mt][nt][q] = 0.f;

    const uint4* wsrc = (const uint4*)(g_wqkvh + (size_t)(br * 12) * 1024);
    {
        #pragma unroll
        for (int i = 0; i < 2; i++) cp16(bb_addr + (i * 256 + tid) * 16, wsrc + i * 256 + tid);
        CP_COMMIT();
    }
    for (int s = 0; s < 12; s++) {
        if (s < 11) {
            const uint4* s4 = wsrc + (s + 1) * 512;
            uint32_t db = bb_addr + ((s + 1) & 1) * 8192;
            #pragma unroll
            for (int i = 0; i < 2; i++) cp16(db + (i * 256 + tid) * 16, s4 + i * 256 + tid);
            CP_COMMIT();
            CP_WAIT1();
        } else CP_WAIT0();
        __syncthreads();
        int kc = s & 3;
        const uint2* Bu = (const uint2*)((char*)sm + 98304 + (s & 1) * 8192);
        const uint4* Au = (const uint4*)AXh;
        #pragma unroll
        for (int kb2 = 0; kb2 < 2; kb2++) {
            uint32_t a[4][4], b[4][2];
            #pragma unroll
            for (int mt = 0; mt < 4; mt++)
                *(uint4*)a[mt] = Au[((kc * 2 + kb2) * 8 + mwarp * 4 + mt) * 32 + tg * 8 + g];
            #pragma unroll
            for (int nt = 0; nt < 4; nt++)
                *(uint2*)b[nt] = Bu[((kb2 * 16 + nwarp * 4 + nt) * 4 + tg) * 8 + g];
            #pragma unroll
            for (int mt = 0; mt < 4; mt++)
                #pragma unroll
                for (int nt = 0; nt < 4; nt++)
                    mma16(d[mt][nt], a[mt], b[nt]);
        }
        __syncthreads();
        if (kc == 3) {
            int nb = s >> 2;
            uint32_t* Qw = (uint32_t*)QAh;
            uint32_t* Kw = (uint32_t*)KBh;
            #pragma unroll
            for (int mt = 0; mt < 4; mt++) {
                #pragma unroll
                for (int nt = 0; nt < 4; nt++) {
                    int row = mwarp * 64 + mt * 16 + g;
                    int col0 = nwarp * 32 + nt * 8 + 2 * tg;
                    if (nb == 0) {
                        Qw[a16h(row, col0) >> 1]     = packh2(d[mt][nt][0], d[mt][nt][1]);
                        Qw[a16h(row + 8, col0) >> 1] = packh2(d[mt][nt][2], d[mt][nt][3]);
                    } else if (nb == 1) {
                        Kw[bfh(col0, row) >> 1]      = packh2(d[mt][nt][0], d[mt][nt][1]);
                        Kw[bfh(col0, row + 8) >> 1]  = packh2(d[mt][nt][2], d[mt][nt][3]);
                    } else {
                        AXh[bfh(row, col0)]         = __float2half_rn(d[mt][nt][0]);
                        AXh[bfh(row, col0 + 1)]     = __float2half_rn(d[mt][nt][1]);
                        AXh[bfh(row + 8, col0)]     = __float2half_rn(d[mt][nt][2]);
                        AXh[bfh(row + 8, col0 + 1)] = __float2half_rn(d[mt][nt][3]);
                    }
                    #pragma unroll
                    for (int q = 0; q < 4; q++) d[mt][nt][q] = 0.f;
                }
            }
            __syncthreads();
        }
    }

    int w = wid >> 2, h = (wid >> 1) & 1, half = wid & 1;
    {
        const uint4* Qa = (const uint4*)QAh;
        const uint2* Kb = (const uint2*)KBh;
        #pragma unroll
        for (int kbl = 0; kbl < 4; kbl++) {
            uint32_t a[4][4], b[4][2];
            #pragma unroll
            for (int mt = 0; mt < 4; mt++)
                *(uint4*)a[mt] = Qa[((h * 4 + kbl) * 8 + w * 4 + mt) * 32 + tg * 8 + g];
            int kc2 = h * 2 + (kbl >> 1), kb2 = kbl & 1;
            #pragma unroll
            for (int nt = 0; nt < 4; nt++)
                *(uint2*)b[nt] = Kb[kc2 * 1024 + ((kb2 * 16 + w * 8 + half * 4 + nt) * 4 + tg) * 8 + g];
            #pragma unroll
            for (int mt = 0; mt < 4; mt++)
                #pragma unroll
                for (int nt = 0; nt < 4; nt++)
                    mma16(d[mt][nt], a[mt], b[nt]);
        }
    }
    __syncthreads();

    const float* bias = g_bias + (br * 2 + h) * 4096;
    #pragma unroll
    for (int mt = 0; mt < 4; mt++) {
        #pragma unroll
        for (int nt = 0; nt < 4; nt++) {
            int rr = mt * 16 + g, cc = half * 32 + nt * 8 + 2 * tg;
            float2 b0 = *(const float2*)(bias + rr * 64 + cc);
            float2 b1 = *(const float2*)(bias + (rr + 8) * 64 + cc);
            d[mt][nt][0] = d[mt][nt][0] * 0.125f + b0.x;
            d[mt][nt][1] = d[mt][nt][1] * 0.125f + b0.y;
            d[mt][nt][2] = d[mt][nt][2] * 0.125f + b1.x;
            d[mt][nt][3] = d[mt][nt][3] * 0.125f + b1.y;
        }
    }
    int whb = ((w * 2 + h) * 2 + half) * 64;
    #pragma unroll
    for (int mt = 0; mt < 4; mt++) {
        float m0 = -1e30f, m1 = -1e30f;
        #pragma unroll
        for (int nt = 0; nt < 4; nt++) {
            m0 = fmaxf(m0, fmaxf(d[mt][nt][0], d[mt][nt][1]));
            m1 = fmaxf(m1, fmaxf(d[mt][nt][2], d[mt][nt][3]));
        }
        m0 = fmaxf(m0, __shfl_xor_sync(~0u, m0, 1)); m0 = fmaxf(m0, __shfl_xor_sync(~0u, m0, 2));
        m1 = fmaxf(m1, __shfl_xor_sync(~0u, m1, 1)); m1 = fmaxf(m1, __shfl_xor_sync(~0u, m1, 2));
        red_max[whb + mt * 16 + g] = m0;
        red_max[whb + mt * 16 + g + 8] = m1;
    }
    __syncthreads();
    int whb0 = ((w * 2 + h) * 2) * 64;
    #pragma unroll
    for (int mt = 0; mt < 4; mt++) {
        float M0 = fmaxf(red_max[whb0 + mt * 16 + g], red_max[whb0 + 64 + mt * 16 + g]);
        float M1 = fmaxf(red_max[whb0 + mt * 16 + g + 8], red_max[whb0 + 64 + mt * 16 + g + 8]);
        float s0 = 0.f, s1 = 0.f;
        #pragma unroll
        for (int nt = 0; nt < 4; nt++) {
            d[mt][nt][0] = expf(d[mt][nt][0] - M0); s0 += d[mt][nt][0];
            d[mt][nt][1] = expf(d[mt][nt][1] - M0); s0 += d[mt][nt][1];
            d[mt][nt][2] = expf(d[mt][nt][2] - M1); s1 += d[mt][nt][2];
            d[mt][nt][3] = expf(d[mt][nt][3] - M1); s1 += d[mt][nt][3];
        }
        s0 += __shfl_xor_sync(~0u, s0, 1); s0 += __shfl_xor_sync(~0u, s0, 2);
        s1 += __shfl_xor_sync(~0u, s1, 1); s1 += __shfl_xor_sync(~0u, s1, 2);
        red_sum[whb + mt * 16 + g] = s0;
        red_sum[whb + mt * 16 + g + 8] = s1;
    }
    __syncthreads();
    {
        uint32_t* Pw = (uint32_t*)QAh;
        #pragma unroll
        for (int mt = 0; mt < 4; mt++) {
            float i0 = 1.f / (red_sum[whb0 + mt * 16 + g] + red_sum[whb0 + 64 + mt * 16 + g]);
            float i1 = 1.f / (red_sum[whb0 + mt * 16 + g + 8] + red_sum[whb0 + 64 + mt * 16 + g + 8]);
            #pragma unroll
            for (int nt = 0; nt < 4; nt++) {
                int row = w * 64 + mt * 16 + g;
                int m0 = half * 32 + nt * 8 + 2 * tg;
                Pw[a16h(row, h * 64 + m0) >> 1]     = packh2(d[mt][nt][0] * i0, d[mt][nt][1] * i0);
                Pw[a16h(row + 8, h * 64 + m0) >> 1] = packh2(d[mt][nt][2] * i1, d[mt][nt][3] * i1);
                #pragma unroll
                for (int q = 0; q < 4; q++) d[mt][nt][q] = 0.f;
            }
        }
    }
    __syncthreads();

    {
        const uint4* Pa = (const uint4*)QAh;
        const uint2* Vb = (const uint2*)AXh;
        #pragma unroll
        for (int kbl = 0; kbl < 4; kbl++) {
            uint32_t a[4][4], b[4][2];
            #pragma unroll
            for (int mt = 0; mt < 4; mt++)
                *(uint4*)a[mt] = Pa[((h * 4 + kbl) * 8 + w * 4 + mt) * 32 + tg * 8 + g];
            int kc2 = w * 2 + (kbl >> 1), kb2 = kbl & 1;
            #pragma unroll
            for (int nt = 0; nt < 4; nt++)
                *(uint2*)b[nt] = Vb[kc2 * 1024 + ((kb2 * 16 + h * 8 + half * 4 + nt) * 4 + tg) * 8 + g];
            #pragma unroll
            for (int mt = 0; mt < 4; mt++)
                #pragma unroll
                for (int nt = 0; nt < 4; nt++)
                    mma16(d[mt][nt], a[mt], b[nt]);
        }
    }
    __syncthreads();
    {
        uint32_t* Ow = (uint32_t*)KBh;
        #pragma unroll
        for (int mt = 0; mt < 4; mt++) {
            #pragma unroll
            for (int nt = 0; nt < 4; nt++) {
                int row = w * 64 + mt * 16 + g;
                int col0 = h * 64 + half * 32 + nt * 8 + 2 * tg;
                Ow[a16h(row, col0) >> 1]     = packh2(d[mt][nt][0], d[mt][nt][1]);
                Ow[a16h(row + 8, col0) >> 1] = packh2(d[mt][nt][2], d[mt][nt][3]);
                #pragma unroll
                for (int q = 0; q < 4; q++) d[mt][nt][q] = 0.f;
            }
        }
    }
    __syncthreads();

    const uint4* psrc = (const uint4*)(g_wph + (size_t)(br * 4) * 1024);
    {
        #pragma unroll
        for (int i = 0; i < 2; i++) cp16(bb_addr + (i * 256 + tid) * 16, psrc + i * 256 + tid);
        CP_COMMIT();
    }
    for (int kc = 0; kc < 4; kc++) {
        if (kc < 3) {
            const uint4* s4 = psrc + (kc + 1) * 512;
            uint32_t db = bb_addr + ((kc + 1) & 1) * 8192;
            #pragma unroll
            for (int i = 0; i < 2; i++) cp16(db + (i * 256 + tid) * 16, s4 + i * 256 + tid);
            CP_COMMIT();
            CP_WAIT1();
        } else CP_WAIT0();
        __syncthreads();
        const uint2* Bu = (const uint2*)((char*)sm + 98304 + (kc & 1) * 8192);
        const uint4* Au = (const uint4*)KBh;
        #pragma unroll
        for (int kb2 = 0; kb2 < 2; kb2++) {
            uint32_t a[4][4], b[4][2];
            #pragma unroll
            for (int mt = 0; mt < 4; mt++)
                *(uint4*)a[mt] = Au[((kc * 2 + kb2) * 8 + mwarp * 4 + mt) * 32 + tg * 8 + g];
            #pragma unroll
            for (int nt = 0; nt < 4; nt++)
                *(uint2*)b[nt] = Bu[((kb2 * 16 + nwarp * 4 + nt) * 4 + tg) * 8 + g];
            #pragma unroll
            for (int mt = 0; mt < 4; mt++)
                #pragma unroll
                for (int nt = 0; nt < 4; nt++)
                    mma16(d[mt][nt], a[mt], b[nt]);
        }
        __syncthreads();
    }

    float* Sf = (float*)AXh;
    for (int p = 0; p < 2; p++) {
        __syncthreads();
        if (mwarp == p) {
            #pragma unroll
            for (int mt = 0; mt < 4; mt++) {
                #pragma unroll
                for (int nt = 0; nt < 4; nt++) {
                    #pragma unroll
                    for (int q = 0; q < 4; q++) {
                        int row = mt * 16 + g + (q >> 1) * 8;
                        int col = nwarp * 32 + nt * 8 + 2 * tg + (q & 1);
                        Sf[row * 132 + col] = d[mt][nt][q] + bp[col];
                    }
                }
            }
        }
        __syncthreads();
        int c = tid & 127;
        #pragma unroll
        for (int it = 0; it < 32; it++) {
            int idx = it * 256 + tid;
            int nl = idx >> 7;
            int n = p * 64 + nl;
            int t = tok_t(pair, n, lg, nWb, Wh, Ww);
            g_x1[t * 256 + co + c] = Sf[nl * 132 + c] + g_xn[t * 256 + co + c];
        }
    }
}

// ===========================================================================
// Fused MLP (fp16, 512 thr / 16 warps): LN2 + GEMM1 + GELU + GEMM2 + residual.
// H never leaves smem. Trailing barrier per chunk closes the 2-slot WAR race.
// smem bytes: X frags 65536 @0 | H frags 32768 @65536 |
//             W1 ring 2x8192 @98304 | W2 ring 2x16384 @114688
// ===========================================================================
#define MF_SMEM 147456
__global__ void __launch_bounds__(512, 1) mlp_fused_kernel(
    const float* __restrict__ x, const float* __restrict__ g2, const float* __restrict__ b2,
    const float* __restrict__ b1, const float* __restrict__ b2o, float* __restrict__ out)
{
    extern __shared__ float sm[];
    __half* Xh = (__half*)sm;                      // 32768 halves
    __half* Hh = (__half*)((char*)sm + 65536);     // 16384 halves
    float* S32  = sm + 24576;                      // LN overlay in ring region
    float* tmpS = S32 + 4160;
    float* tmpQ = tmpS + 512;
    float* mu   = tmpQ + 512;
    float* rs   = mu + 128;

    int tid = threadIdx.x, wid = tid >> 5, lane = tid & 31;
    int t0 = blockIdx.x * 128;
    uint32_t w1base = smem_u32(sm) + 98304;
    uint32_t w2base = smem_u32(sm) + 114688;

    // ---- LN2: stats + raw fp16 stash ----
    float accS = 0.f, accQ = 0.f;
    int nrole = tid & 127, part = tid >> 7;
    for (int cb = 0; cb < 8; cb++) {
        __syncthreads();
        #pragma unroll
        for (int it = 0; it < 8; it++) {
            int idx = it * 512 + tid;
            int n = idx & 127, cl = idx >> 7;
            S32[cl * 129 + n] = x[(size_t)(cb * 32 + cl) * HW + t0 + n];
        }
        __syncthreads();
        #pragma unroll
        for (int it = 0; it < 8; it++) {
            int idx = it * 512 + tid;
            int c = idx & 31, n = idx >> 5;
            S32[c * 129 + n] += g_x1[(size_t)(t0 + n) * 256 + cb * 32 + c];
        }
        __syncthreads();
        #pragma unroll
        for (int i = 0; i < 8; i++) {
            int cl = part * 8 + i;
            float v = S32[cl * 129 + nrole];
            accS += v; accQ += v * v;
            Xh[a16h(nrole, cb * 32 + cl)] = __float2half_rn(v);
        }
    }
    __syncthreads();
    tmpS[part * 128 + nrole] = accS;
    tmpQ[part * 128 + nrole] = accQ;
    __syncthreads();
    if (tid < 128) {
        float s1 = tmpS[tid] + tmpS[128 + tid] + tmpS[256 + tid] + tmpS[384 + tid];
        float s2 = tmpQ[tid] + tmpQ[128 + tid] + tmpQ[256 + tid] + tmpQ[384 + tid];
        float m = s1 * (1.f / 256.f);
        mu[tid] = m;
        rs[tid] = rsqrtf(s2 * (1.f / 256.f) - m * m + 1e-5f);
    }
    __syncthreads();
    {
        int tok = tid & 127, qr = tid >> 7;
        float m = mu[tok], r = rs[tok];
        for (int c = qr * 64; c < qr * 64 + 64; c++) {
            int hi = a16h(tok, c);
            float v = __half2float(Xh[hi]);
            Xh[hi] = __float2half_rn((v - m) * r * __ldg(g2 + c) + __ldg(b2 + c));
        }
    }
    __syncthreads();

    // ---- fused GEMM1 -> GELU -> GEMM2 over 8 hidden blocks of 128 ----
    int mwarp = wid >> 2, nwarp = wid & 3;
    int g = lane >> 2, tg = lane & 3;
    const uint4* Xu = (const uint4*)Xh;
    const uint4* Hu = (const uint4*)Hh;
    uint32_t* Hw = (uint32_t*)Hh;

    float d2[2][8][4];
    #pragma unroll
    for (int mt = 0; mt < 2; mt++)
        #pragma unroll
        for (int nt = 0; nt < 8; nt++)
            #pragma unroll
            for (int q = 0; q < 4; q++) d2[mt][nt][q] = 0.f;

    {   // prefetch W1 chunk (hb=0, c=0) -> slot 0
        const uint4* src = (const uint4*)g_w1h;
        cp16(w1base + tid * 16, src + tid);
        CP_COMMIT();
    }

    for (int hb = 0; hb < 8; hb++) {
        float d1[2][4][4];
        #pragma unroll
        for (int mt = 0; mt < 2; mt++)
            #pragma unroll
            for (int nt = 0; nt < 4; nt++)
                #pragma unroll
                for (int q = 0; q < 4; q++) d1[mt][nt][q] = 0.f;

        // ---- GEMM1: 8 W1 chunks (k32 x n128) ----
        for (int c = 0; c < 8; c++) {
            if (c < 7) {
                const uint4* src = (const uint4*)g_w1h + (size_t)(hb * 8 + c + 1) * 512;
                uint32_t db = w1base + (uint32_t)(((c + 1) & 1) * 8192);
                cp16(db + tid * 16, src + tid);
            } else {
                const uint4* src = (const uint4*)g_w2h + (size_t)(hb * 4) * 1024;
                #pragma unroll
                for (int i = 0; i < 2; i++) cp16(w2base + (i * 512 + tid) * 16, src + i * 512 + tid);
            }
            CP_COMMIT();
            CP_WAIT1();
            __syncthreads();
            const uint2* Bu = (const uint2*)((char*)sm + 98304 + (c & 1) * 8192);
            #pragma unroll
            for (int kb2 = 0; kb2 < 2; kb2++) {
                uint32_t a[2][4], b[4][2];
                #pragma unroll
                for (int mt = 0; mt < 2; mt++)
                    *(uint4*)a[mt] = Xu[((c * 2 + kb2) * 8 + mwarp * 2 + mt) * 32 + tg * 8 + g];
                #pragma unroll
                for (int nt = 0; nt < 4; nt++)
                    *(uint2*)b[nt] = Bu[((kb2 * 16 + nwarp * 4 + nt) * 4 + tg) * 8 + g];
                #pragma unroll
                for (int mt = 0; mt < 2; mt++)
                    #pragma unroll
                    for (int nt = 0; nt < 4; nt++)
                        mma16(d1[mt][nt], a[mt], b[nt]);
            }
            __syncthreads();   // FIX: drain readers of this slot before it is re-filled
        }

        // ---- GELU epilogue -> H frags in smem ----
        #pragma unroll
        for (int mt = 0; mt < 2; mt++) {
            #pragma unroll
            for (int nt = 0; nt < 4; nt++) {
                int row0 = mwarp * 32 + mt * 16 + g;
                int col0 = nwarp * 32 + nt * 8 + 2 * tg;    // local 0..127
                int cg = hb * 128 + col0;
                float b0v = b1[cg], b1v = b1[cg + 1];
                float v0 = gelu(d1[mt][nt][0] + b0v);
                float v1 = gelu(d1[mt][nt][1] + b1v);
                float v2 = gelu(d1[mt][nt][2] + b0v);
                float v3 = gelu(d1[mt][nt][3] + b1v);
                Hw[a16h(row0, col0) >> 1]     = packh2(v0, v1);
                Hw[a16h(row0 + 8, col0) >> 1] = packh2(v2, v3);
            }
        }
        __syncthreads();   // H visible before GEMM2 reads

        // ---- GEMM2: 4 W2 chunks (k32 x n256), accumulate d2 ----
        for (int c2 = 0; c2 < 4; c2++) {
            if (c2 < 3) {
                const uint4* src = (const uint4*)g_w2h + (size_t)(hb * 4 + c2 + 1) * 1024;
                uint32_t db = w2base + (uint32_t)(((c2 + 1) & 1) * 16384);
                #pragma unroll
                for (int i = 0; i < 2; i++) cp16(db + (i * 512 + tid) * 16, src + i * 512 + tid);
            } else if (hb < 7) {
                const uint4* src = (const uint4*)g_w1h + (size_t)((hb + 1) * 8) * 512;
                cp16(w1base + tid * 16, src + tid);
            }
            CP_COMMIT();
            CP_WAIT1();
            __syncthreads();
            const uint2* Bu = (const uint2*)((char*)sm + 114688 + (c2 & 1) * 16384);
            #pragma unroll
            for (int kb2 = 0; kb2 < 2; kb2++) {
                uint32_t a[2][4], b[8][2];
                #pragma unroll
                for (int mt = 0; mt < 2; mt++)
                    *(uint4*)a[mt] = Hu[((c2 * 2 + kb2) * 8 + mwarp * 2 + mt) * 32 + tg * 8 + g];
                #pragma unroll
                for (int nt = 0; nt < 8; nt++)
                    *(uint2*)b[nt] = Bu[((kb2 * 32 + nwarp * 8 + nt) * 4 + tg) * 8 + g];
                #pragma unroll
                for (int mt = 0; mt < 2; mt++)
                    #pragma unroll
                    for (int nt = 0; nt < 8; nt++)
                        mma16(d2[mt][nt], a[mt], b[nt]);
            }
            __syncthreads();   // FIX: drain readers of this slot before it is re-filled
        }
    }

    // ---- final epilogue: residual + NCHW store ----
    float* S = sm;        // overlay on X frags (dead now)
    for (int p = 0; p < 2; p++) {
        __syncthreads();
        #pragma unroll 4
        for (int it = 0; it < 32; it++) {
            int idx = it * 512 + tid;
            int c = idx & 255, nl = idx >> 8;
            S[c * 69 + nl] = g_x1[(size_t)(t0 + p * 64 + nl) * 256 + c];
        }
        __syncthreads();
        if ((mwarp >> 1) == p) {
            #pragma unroll
            for (int mt = 0; mt < 2; mt++) {
                #pragma unroll
                for (int nt = 0; nt < 8; nt++) {
                    int row0 = mwarp * 32 + mt * 16 + g;
                    int col0 = nwarp * 64 + nt * 8 + 2 * tg;
                    #pragma unroll
                    for (int q = 0; q < 4; q++) {
                        int col = col0 + (q & 1);
                        int row = row0 + (q >> 1) * 8;
                        float v = d2[mt][nt][q] + b2o[col]
                                + x[(size_t)col * HW + t0 + row] + S[col * 69 + (row - p * 64)];
                        out[(size_t)col * HW + t0 + row] = v;
                    }
                }
            }
        }
    }
}

// ---------------------------------------------------------------------------
extern "C" void kernel_launch(void* const* d_in, const int* in_sizes, int n_in,
                              void* d_out, int out_size) {
    const float* x        = (const float*)d_in[0];
    const float* norm1_g  = (const float*)d_in[1];
    const float* norm1_b  = (const float*)d_in[2];
    const float* qkv_r    = (const float*)d_in[3];
    const float* proj_r_w = (const float*)d_in[4];
    const float* proj_r_b = (const float*)d_in[5];
    const float* table_r  = (const float*)d_in[6];
    const float* qkv_a    = (const float*)d_in[7];
    const float* proj_a_w = (const float*)d_in[8];
    const float* proj_a_b = (const float*)d_in[9];
    const float* table_a  = (const float*)d_in[10];
    const float* norm2_g  = (const float*)d_in[11];
    const float* norm2_b  = (const float*)d_in[12];
    const float* mlp_w1   = (const float*)d_in[13];
    const float* mlp_b1   = (const float*)d_in[14];
    const float* mlp_w2   = (const float*)d_in[15];
    const float* mlp_b2   = (const float*)d_in[16];
    float* out = (float*)d_out;

    cudaFuncSetAttribute(attn_kernel, cudaFuncAttributeMaxDynamicSharedMemorySize, ATTN_SMEM);
    cudaFuncSetAttribute(mlp_fused_kernel, cudaFuncAttributeMaxDynamicSharedMemorySize, MF_SMEM);

    ln1_kernel<<<2048, 256>>>(x, norm1_g, norm1_b);
    bias_kernel<<<1, 256>>>(table_r, table_a);
    wfmt_kernel<<<512, 256>>>(mlp_w1, mlp_w2);
    wfmt2h_kernel<<<128, 256>>>(qkv_r, proj_r_w, qkv_a, proj_a_w);
    attn_kernel<<<dim3(512, 2), 256, ATTN_SMEM>>>(proj_r_b, proj_a_b);
    mlp_fused_kernel<<<512, 512, MF_SMEM>>>(x, norm2_g, norm2_b, mlp_b1, mlp_b2, out);
}

// round 17
// speedup vs baseline: 1.0208x; 1.0070x over previous
#include <cuda_runtime.h>
#include <cuda_fp16.h>
#include <cstdint>

#define HW 65536

__device__ float g_xn[HW * 256];
__device__ float g_x1[HW * 256];
__device__ float g_bias[2 * 2 * 64 * 64];
__device__ uint2 g_w1h[65536];              // W1 fp16 frag chunks [hb*8+kc][1024] (k32 x n128)
__device__ uint2 g_w2h[65536];              // W2 fp16 frag chunks [kc][2048]      (k32 x n256)
__device__ uint2 g_wqkvh[24576];            // Wqkv fp16 frags [br][nb][kc][1024]
__device__ uint2 g_wph[8192];               // Wproj fp16 frags [br][kc][1024]

__device__ __forceinline__ uint32_t smem_u32(const void* p) {
    uint32_t a;
    asm("{ .reg .u64 t; cvta.to.shared.u64 t, %1; cvt.u32.u64 %0, t; }" : "=r"(a) : "l"(p));
    return a;
}
__device__ __forceinline__ void cp16(uint32_t dst, const void* src) {
    asm volatile("cp.async.cg.shared.global [%0], [%1], 16;" :: "r"(dst), "l"(src));
}
#define CP_COMMIT() asm volatile("cp.async.commit_group;" ::: "memory")
#define CP_WAIT1()  asm volatile("cp.async.wait_group 1;" ::: "memory")
#define CP_WAIT0()  asm volatile("cp.async.wait_group 0;" ::: "memory")

__device__ __forceinline__ void mma16(float* d, const uint32_t* a, const uint32_t* b) {
    asm volatile("mma.sync.aligned.m16n8k16.row.col.f32.f16.f16.f32 "
        "{%0,%1,%2,%3}, {%4,%5,%6,%7}, {%8,%9}, {%0,%1,%2,%3};"
        : "+f"(d[0]), "+f"(d[1]), "+f"(d[2]), "+f"(d[3])
        : "r"(a[0]), "r"(a[1]), "r"(a[2]), "r"(a[3]), "r"(b[0]), "r"(b[1]));
}
__device__ __forceinline__ uint32_t packh2(float lo, float hi) {
    __half2 h = __floats2half2_rn(lo, hi);
    return *(uint32_t*)&h;
}
__device__ __forceinline__ float gelu(float v) {
    return 0.5f * v * (1.f + erff(v * 0.70710678118f));
}
// fp16 A-fragment half-index (verified): element (tok, k=c)
__device__ __forceinline__ int a16h(int tok, int c) {
    return ((((c >> 4) * 8 + (tok >> 4)) * 32 + ((c & 7) >> 1) * 8 + (tok & 7)) * 4
            + ((tok >> 3) & 1) + 2 * ((c >> 3) & 1)) * 2 + (c & 1);
}
// fp16 B-fragment half-index, N=128 region of k32 chunks (verified)
__device__ __forceinline__ int bfh(int k, int n) {
    return (k >> 5) * 4096
         + (((((k >> 4) & 1) * 16 + (n >> 3)) * 4 + ((k & 7) >> 1)) * 8 + (n & 7)) * 4
         + ((k >> 3) & 1) * 2 + (k & 1);
}

// ---------------- LN1: 64 tokens/CTA, float2 loads ----------------
#define LN1_SMEM (16640 * 4 + 512)
__global__ void __launch_bounds__(256) ln1_kernel(const float* __restrict__ x,
                                                  const float* __restrict__ g,
                                                  const float* __restrict__ b) {
    extern __shared__ float ls[];
    float* s  = ls;                 // [256][65]
    float* mu = ls + 16640;
    float* rs = mu + 64;
    int t0 = blockIdx.x * 64;
    int tid = threadIdx.x, lane = tid & 31, wid = tid >> 5;
    #pragma unroll
    for (int c = wid; c < 256; c += 8) {
        float2 v = *(const float2*)(x + (size_t)c * HW + t0 + 2 * lane);
        s[c * 65 + 2 * lane] = v.x;
        s[c * 65 + 2 * lane + 1] = v.y;
    }
    __syncthreads();
    {
        int tok = tid >> 2, part = tid & 3;
        float sum = 0.f, sq = 0.f;
        #pragma unroll 8
        for (int i = 0; i < 64; i++) {
            float v = s[(part * 64 + i) * 65 + tok];
            sum += v; sq += v * v;
        }
        sum += __shfl_xor_sync(~0u, sum, 1); sq += __shfl_xor_sync(~0u, sq, 1);
        sum += __shfl_xor_sync(~0u, sum, 2); sq += __shfl_xor_sync(~0u, sq, 2);
        if (part == 0) {
            float m = sum * (1.f / 256.f);
            mu[tok] = m;
            rs[tok] = rsqrtf(sq * (1.f / 256.f) - m * m + 1e-5f);
        }
    }
    __syncthreads();
    float gc = g[tid], bc = b[tid];
    #pragma unroll 4
    for (int k = 0; k < 64; k++)
        g_xn[(size_t)(t0 + k) * 256 + tid] = (s[tid * 65 + k] - mu[k]) * rs[k] * gc + bc;
}

// ---------------- bias tables ----------------
__global__ void bias_kernel(const float* __restrict__ tr, const float* __restrict__ ta) {
    for (int idx = threadIdx.x; idx < 16384; idx += blockDim.x) {
        int br = idx >> 13, rem = idx & 8191;
        int h = rem >> 12, n = (rem >> 6) & 63, m = rem & 63;
        int Wh = br ? 4 : 16, Ww = br ? 16 : 4, lg = br ? 4 : 2;
        int ridx = ((n >> lg) - (m >> lg) + Wh - 1) * (2 * Ww - 1) + ((n & (Ww - 1)) - (m & (Ww - 1)) + Ww - 1);
        g_bias[idx] = (br ? ta : tr)[ridx * 2 + h];
    }
}

// ---------------- MLP weight pre-format ----------------
__global__ void __launch_bounds__(256) wfmt_kernel(const float* __restrict__ W1,
                                                   const float* __restrict__ W2) {
    int idx = blockIdx.x * 256 + threadIdx.x;      // 0..131071
    if (idx < 65536) {
        int i = idx & 1023;
        int g = i & 7, tg = (i >> 3) & 3, nt = (i >> 5) & 15, kb2 = i >> 9;
        int chunk = idx >> 10;                     // hb*8 + kc
        int hb = chunk >> 3, kc = chunk & 7;
        int col = hb * 128 + nt * 8 + g;
        int kbase = kc * 32 + kb2 * 16 + 2 * tg;
        float w0 = W1[(size_t)kbase * 1024 + col];
        float w1 = W1[(size_t)(kbase + 1) * 1024 + col];
        float w2 = W1[(size_t)(kbase + 8) * 1024 + col];
        float w3 = W1[(size_t)(kbase + 9) * 1024 + col];
        g_w1h[chunk * 1024 + ((kb2 * 16 + nt) * 4 + tg) * 8 + g]
            = make_uint2(packh2(w0, w1), packh2(w2, w3));
    } else {
        int u = idx - 65536;
        int g = u & 7, tg = (u >> 3) & 3, nt = (u >> 5) & 31;
        int kb2 = (u >> 10) & 1, kc = u >> 11;
        int col = nt * 8 + g;
        int kbase = kc * 32 + kb2 * 16 + 2 * tg;
        float w0 = W2[(size_t)kbase * 256 + col];
        float w1 = W2[(size_t)(kbase + 1) * 256 + col];
        float w2 = W2[(size_t)(kbase + 8) * 256 + col];
        float w3 = W2[(size_t)(kbase + 9) * 256 + col];
        g_w2h[kc * 2048 + ((kb2 * 32 + nt) * 4 + tg) * 8 + g]
            = make_uint2(packh2(w0, w1), packh2(w2, w3));
    }
}

// ---------------- attention weight pre-format (fp16 frags) ----------------
__global__ void __launch_bounds__(256) wfmt2h_kernel(
    const float* __restrict__ Wq_r, const float* __restrict__ Wp_r,
    const float* __restrict__ Wq_a, const float* __restrict__ Wp_a)
{
    int idx = blockIdx.x * 256 + threadIdx.x;      // 0..32767 (uint2 units)
    int i = idx & 1023;
    int g = i & 7, tg = (i >> 3) & 3, nt = (i >> 5) & 15, kb2 = i >> 9;
    const float* W; int ld, col, kc; uint2* dst; int out;
    if (idx < 24576) {
        int br = idx / 12288, r = idx % 12288;
        int nb = r >> 12; kc = (r >> 10) & 3;
        W = br ? Wq_a : Wq_r; ld = 384;
        col = nb * 128 + nt * 8 + g;
        dst = g_wqkvh; out = idx;
    } else {
        int j = idx - 24576;
        int br = j >> 12; kc = (j >> 10) & 3;
        W = br ? Wp_a : Wp_r; ld = 128;
        col = nt * 8 + g;
        dst = g_wph; out = j;
    }
    int kbase = kc * 32 + kb2 * 16 + 2 * tg;
    float w0 = W[(size_t)kbase * ld + col];
    float w1 = W[(size_t)(kbase + 1) * ld + col];
    float w2 = W[(size_t)(kbase + 8) * ld + col];
    float w3 = W[(size_t)(kbase + 9) * ld + col];
    dst[out] = make_uint2(packh2(w0, w1), packh2(w2, w3));
}

// ===========================================================================
// fp16 tensor-core window attention (unchanged from R12). 2 CTA/SM.
// ===========================================================================
#define ATTN_SMEM 114688
__device__ __forceinline__ int tok_t(int pair, int n, int lg, int nWb, int Wh, int Ww) {
    int w = n >> 6, nl = n & 63;
    int wi = pair * 2 + w;
    int hb = wi / nWb, wb = wi - hb * nWb;
    return ((hb * Wh + (nl >> lg)) << 8) + wb * Ww + (nl & (Ww - 1));
}

__global__ void __launch_bounds__(256, 2) attn_kernel(
    const float* __restrict__ bp_r, const float* __restrict__ bp_a)
{
    extern __shared__ float sm[];
    __half*  AXh = (__half*)sm;
    __half*  QAh = (__half*)((char*)sm + 32768);
    __half*  KBh = (__half*)((char*)sm + 65536);
    uint32_t bb_addr = smem_u32(sm) + 98304;
    float* red_max = (float*)KBh;
    float* red_sum = (float*)KBh + 512;

    int br = blockIdx.y;
    int co = br ? 128 : 0, lg = br ? 4 : 2;
    int Ww = 1 << lg, nWb = br ? 16 : 64, Wh = br ? 4 : 16;
    const float* bp = br ? bp_a : bp_r;
    int pair = blockIdx.x;
    int tid = threadIdx.x, wid = tid >> 5, lane = tid & 31;
    int g = lane >> 2, tg = lane & 3;

    {
        int k = tid & 127;
        #pragma unroll 2
        for (int it = 0; it < 64; it++) {
            int idx = it * 256 + tid;
            int n = idx >> 7;
            int t = tok_t(pair, n, lg, nWb, Wh, Ww);
            QAh[k * 130 + n] = __float2half_rn(g_xn[t * 256 + co + k]);
        }
    }
    __syncthreads();
    {
        uint4* AXu4 = (uint4*)AXh;
        #pragma unroll
        for (int i = 0; i < 8; i++) {
            int p = wid * 8 + i;
            int kb = p >> 3, mt = p & 7;
            int c0 = kb * 16 + 2 * tg, row = mt * 16 + g;
            uint4 u;
            u.x = packh2(__half2float(QAh[c0 * 130 + row]),       __half2float(QAh[(c0 + 1) * 130 + row]));
            u.y = packh2(__half2float(QAh[c0 * 130 + row + 8]),   __half2float(QAh[(c0 + 1) * 130 + row + 8]));
            u.z = packh2(__half2float(QAh[(c0 + 8) * 130 + row]), __half2float(QAh[(c0 + 9) * 130 + row]));
            u.w = packh2(__half2float(QAh[(c0 + 8) * 130 + row + 8]), __half2float(QAh[(c0 + 9) * 130 + row + 8]));
            AXu4[(kb * 8 + mt) * 32 + tg * 8 + g] = u;
        }
    }
    __syncthreads();

    int mwarp = wid >> 2, nwarp = wid & 3;
    float d[4][4][4];
    #pragma unroll
    for (int mt = 0; mt < 4; mt++)
        #pragma unroll
        for (int nt = 0; nt < 4; nt++)
            #pragma unroll
            for (int q = 0; q < 4; q++) d[mt][nt][q] = 0.f;

    const uint4* wsrc = (const uint4*)(g_wqkvh + (size_t)(br * 12) * 1024);
    {
        #pragma unroll
        for (int i = 0; i < 2; i++) cp16(bb_addr + (i * 256 + tid) * 16, wsrc + i * 256 + tid);
        CP_COMMIT();
    }
    for (int s = 0; s < 12; s++) {
        if (s < 11) {
            const uint4* s4 = wsrc + (s + 1) * 512;
            uint32_t db = bb_addr + ((s + 1) & 1) * 8192;
            #pragma unroll
            for (int i = 0; i < 2; i++) cp16(db + (i * 256 + tid) * 16, s4 + i * 256 + tid);
            CP_COMMIT();
            CP_WAIT1();
        } else CP_WAIT0();
        __syncthreads();
        int kc = s & 3;
        const uint2* Bu = (const uint2*)((char*)sm + 98304 + (s & 1) * 8192);
        const uint4* Au = (const uint4*)AXh;
        #pragma unroll
        for (int kb2 = 0; kb2 < 2; kb2++) {
            uint32_t a[4][4], b[4][2];
            #pragma unroll
            for (int mt = 0; mt < 4; mt++)
                *(uint4*)a[mt] = Au[((kc * 2 + kb2) * 8 + mwarp * 4 + mt) * 32 + tg * 8 + g];
            #pragma unroll
            for (int nt = 0; nt < 4; nt++)
                *(uint2*)b[nt] = Bu[((kb2 * 16 + nwarp * 4 + nt) * 4 + tg) * 8 + g];
            #pragma unroll
            for (int mt = 0; mt < 4; mt++)
                #pragma unroll
                for (int nt = 0; nt < 4; nt++)
                    mma16(d[mt][nt], a[mt], b[nt]);
        }
        __syncthreads();
        if (kc == 3) {
            int nb = s >> 2;
            uint32_t* Qw = (uint32_t*)QAh;
            uint32_t* Kw = (uint32_t*)KBh;
            #pragma unroll
            for (int mt = 0; mt < 4; mt++) {
                #pragma unroll
                for (int nt = 0; nt < 4; nt++) {
                    int row = mwarp * 64 + mt * 16 + g;
                    int col0 = nwarp * 32 + nt * 8 + 2 * tg;
                    if (nb == 0) {
                        Qw[a16h(row, col0) >> 1]     = packh2(d[mt][nt][0], d[mt][nt][1]);
                        Qw[a16h(row + 8, col0) >> 1] = packh2(d[mt][nt][2], d[mt][nt][3]);
                    } else if (nb == 1) {
                        Kw[bfh(col0, row) >> 1]      = packh2(d[mt][nt][0], d[mt][nt][1]);
                        Kw[bfh(col0, row + 8) >> 1]  = packh2(d[mt][nt][2], d[mt][nt][3]);
                    } else {
                        AXh[bfh(row, col0)]         = __float2half_rn(d[mt][nt][0]);
                        AXh[bfh(row, col0 + 1)]     = __float2half_rn(d[mt][nt][1]);
                        AXh[bfh(row + 8, col0)]     = __float2half_rn(d[mt][nt][2]);
                        AXh[bfh(row + 8, col0 + 1)] = __float2half_rn(d[mt][nt][3]);
                    }
                    #pragma unroll
                    for (int q = 0; q < 4; q++) d[mt][nt][q] = 0.f;
                }
            }
            __syncthreads();
        }
    }

    int w = wid >> 2, h = (wid >> 1) & 1, half = wid & 1;
    {
        const uint4* Qa = (const uint4*)QAh;
        const uint2* Kb = (const uint2*)KBh;
        #pragma unroll
        for (int kbl = 0; kbl < 4; kbl++) {
            uint32_t a[4][4], b[4][2];
            #pragma unroll
            for (int mt = 0; mt < 4; mt++)
                *(uint4*)a[mt] = Qa[((h * 4 + kbl) * 8 + w * 4 + mt) * 32 + tg * 8 + g];
            int kc2 = h * 2 + (kbl >> 1), kb2 = kbl & 1;
            #pragma unroll
            for (int nt = 0; nt < 4; nt++)
                *(uint2*)b[nt] = Kb[kc2 * 1024 + ((kb2 * 16 + w * 8 + half * 4 + nt) * 4 + tg) * 8 + g];
            #pragma unroll
            for (int mt = 0; mt < 4; mt++)
                #pragma unroll
                for (int nt = 0; nt < 4; nt++)
                    mma16(d[mt][nt], a[mt], b[nt]);
        }
    }
    __syncthreads();

    const float* bias = g_bias + (br * 2 + h) * 4096;
    #pragma unroll
    for (int mt = 0; mt < 4; mt++) {
        #pragma unroll
        for (int nt = 0; nt < 4; nt++) {
            int rr = mt * 16 + g, cc = half * 32 + nt * 8 + 2 * tg;
            float2 b0 = *(const float2*)(bias + rr * 64 + cc);
            float2 b1 = *(const float2*)(bias + (rr + 8) * 64 + cc);
            d[mt][nt][0] = d[mt][nt][0] * 0.125f + b0.x;
            d[mt][nt][1] = d[mt][nt][1] * 0.125f + b0.y;
            d[mt][nt][2] = d[mt][nt][2] * 0.125f + b1.x;
            d[mt][nt][3] = d[mt][nt][3] * 0.125f + b1.y;
        }
    }
    int whb = ((w * 2 + h) * 2 + half) * 64;
    #pragma unroll
    for (int mt = 0; mt < 4; mt++) {
        float m0 = -1e30f, m1 = -1e30f;
        #pragma unroll
        for (int nt = 0; nt < 4; nt++) {
            m0 = fmaxf(m0, fmaxf(d[mt][nt][0], d[mt][nt][1]));
            m1 = fmaxf(m1, fmaxf(d[mt][nt][2], d[mt][nt][3]));
        }
        m0 = fmaxf(m0, __shfl_xor_sync(~0u, m0, 1)); m0 = fmaxf(m0, __shfl_xor_sync(~0u, m0, 2));
        m1 = fmaxf(m1, __shfl_xor_sync(~0u, m1, 1)); m1 = fmaxf(m1, __shfl_xor_sync(~0u, m1, 2));
        red_max[whb + mt * 16 + g] = m0;
        red_max[whb + mt * 16 + g + 8] = m1;
    }
    __syncthreads();
    int whb0 = ((w * 2 + h) * 2) * 64;
    #pragma unroll
    for (int mt = 0; mt < 4; mt++) {
        float M0 = fmaxf(red_max[whb0 + mt * 16 + g], red_max[whb0 + 64 + mt * 16 + g]);
        float M1 = fmaxf(red_max[whb0 + mt * 16 + g + 8], red_max[whb0 + 64 + mt * 16 + g + 8]);
        float s0 = 0.f, s1 = 0.f;
        #pragma unroll
        for (int nt = 0; nt < 4; nt++) {
            d[mt][nt][0] = expf(d[mt][nt][0] - M0); s0 += d[mt][nt][0];
            d[mt][nt][1] = expf(d[mt][nt][1] - M0); s0 += d[mt][nt][1];
            d[mt][nt][2] = expf(d[mt][nt][2] - M1); s1 += d[mt][nt][2];
            d[mt][nt][3] = expf(d[mt][nt][3] - M1); s1 += d[mt][nt][3];
        }
        s0 += __shfl_xor_sync(~0u, s0, 1); s0 += __shfl_xor_sync(~0u, s0, 2);
        s1 += __shfl_xor_sync(~0u, s1, 1); s1 += __shfl_xor_sync(~0u, s1, 2);
        red_sum[whb + mt * 16 + g] = s0;
        red_sum[whb + mt * 16 + g + 8] = s1;
    }
    __syncthreads();
    {
        uint32_t* Pw = (uint32_t*)QAh;
        #pragma unroll
        for (int mt = 0; mt < 4; mt++) {
            float i0 = 1.f / (red_sum[whb0 + mt * 16 + g] + red_sum[whb0 + 64 + mt * 16 + g]);
            float i1 = 1.f / (red_sum[whb0 + mt * 16 + g + 8] + red_sum[whb0 + 64 + mt * 16 + g + 8]);
            #pragma unroll
            for (int nt = 0; nt < 4; nt++) {
                int row = w * 64 + mt * 16 + g;
                int m0 = half * 32 + nt * 8 + 2 * tg;
                Pw[a16h(row, h * 64 + m0) >> 1]     = packh2(d[mt][nt][0] * i0, d[mt][nt][1] * i0);
                Pw[a16h(row + 8, h * 64 + m0) >> 1] = packh2(d[mt][nt][2] * i1, d[mt][nt][3] * i1);
                #pragma unroll
                for (int q = 0; q < 4; q++) d[mt][nt][q] = 0.f;
            }
        }
    }
    __syncthreads();

    {
        const uint4* Pa = (const uint4*)QAh;
        const uint2* Vb = (const uint2*)AXh;
        #pragma unroll
        for (int kbl = 0; kbl < 4; kbl++) {
            uint32_t a[4][4], b[4][2];
            #pragma unroll
            for (int mt = 0; mt < 4; mt++)
                *(uint4*)a[mt] = Pa[((h * 4 + kbl) * 8 + w * 4 + mt) * 32 + tg * 8 + g];
            int kc2 = w * 2 + (kbl >> 1), kb2 = kbl & 1;
            #pragma unroll
            for (int nt = 0; nt < 4; nt++)
                *(uint2*)b[nt] = Vb[kc2 * 1024 + ((kb2 * 16 + h * 8 + half * 4 + nt) * 4 + tg) * 8 + g];
            #pragma unroll
            for (int mt = 0; mt < 4; mt++)
                #pragma unroll
                for (int nt = 0; nt < 4; nt++)
                    mma16(d[mt][nt], a[mt], b[nt]);
        }
    }
    __syncthreads();
    {
        uint32_t* Ow = (uint32_t*)KBh;
        #pragma unroll
        for (int mt = 0; mt < 4; mt++) {
            #pragma unroll
            for (int nt = 0; nt < 4; nt++) {
                int row = w * 64 + mt * 16 + g;
                int col0 = h * 64 + half * 32 + nt * 8 + 2 * tg;
                Ow[a16h(row, col0) >> 1]     = packh2(d[mt][nt][0], d[mt][nt][1]);
                Ow[a16h(row + 8, col0) >> 1] = packh2(d[mt][nt][2], d[mt][nt][3]);
                #pragma unroll
                for (int q = 0; q < 4; q++) d[mt][nt][q] = 0.f;
            }
        }
    }
    __syncthreads();

    const uint4* psrc = (const uint4*)(g_wph + (size_t)(br * 4) * 1024);
    {
        #pragma unroll
        for (int i = 0; i < 2; i++) cp16(bb_addr + (i * 256 + tid) * 16, psrc + i * 256 + tid);
        CP_COMMIT();
    }
    for (int kc = 0; kc < 4; kc++) {
        if (kc < 3) {
            const uint4* s4 = psrc + (kc + 1) * 512;
            uint32_t db = bb_addr + ((kc + 1) & 1) * 8192;
            #pragma unroll
            for (int i = 0; i < 2; i++) cp16(db + (i * 256 + tid) * 16, s4 + i * 256 + tid);
            CP_COMMIT();
            CP_WAIT1();
        } else CP_WAIT0();
        __syncthreads();
        const uint2* Bu = (const uint2*)((char*)sm + 98304 + (kc & 1) * 8192);
        const uint4* Au = (const uint4*)KBh;
        #pragma unroll
        for (int kb2 = 0; kb2 < 2; kb2++) {
            uint32_t a[4][4], b[4][2];
            #pragma unroll
            for (int mt = 0; mt < 4; mt++)
                *(uint4*)a[mt] = Au[((kc * 2 + kb2) * 8 + mwarp * 4 + mt) * 32 + tg * 8 + g];
            #pragma unroll
            for (int nt = 0; nt < 4; nt++)
                *(uint2*)b[nt] = Bu[((kb2 * 16 + nwarp * 4 + nt) * 4 + tg) * 8 + g];
            #pragma unroll
            for (int mt = 0; mt < 4; mt++)
                #pragma unroll
                for (int nt = 0; nt < 4; nt++)
                    mma16(d[mt][nt], a[mt], b[nt]);
        }
        __syncthreads();
    }

    float* Sf = (float*)AXh;
    for (int p = 0; p < 2; p++) {
        __syncthreads();
        if (mwarp == p) {
            #pragma unroll
            for (int mt = 0; mt < 4; mt++) {
                #pragma unroll
                for (int nt = 0; nt < 4; nt++) {
                    #pragma unroll
                    for (int q = 0; q < 4; q++) {
                        int row = mt * 16 + g + (q >> 1) * 8;
                        int col = nwarp * 32 + nt * 8 + 2 * tg + (q & 1);
                        Sf[row * 132 + col] = d[mt][nt][q] + bp[col];
                    }
                }
            }
        }
        __syncthreads();
        int c = tid & 127;
        #pragma unroll
        for (int it = 0; it < 32; it++) {
            int idx = it * 256 + tid;
            int nl = idx >> 7;
            int n = p * 64 + nl;
            int t = tok_t(pair, n, lg, nWb, Wh, Ww);
            g_x1[t * 256 + co + c] = Sf[nl * 132 + c] + g_xn[t * 256 + co + c];
        }
    }
}

// ===========================================================================
// Fused MLP (fp16, 512 thr / 16 warps): LN2 + GEMM1 + GELU + GEMM2 + residual.
// 3-slot W rings, ONE barrier per chunk (R11-proven reuse-distance-3 scheme).
// smem bytes: X frags 65536 @0 | H frags 32768 @65536 |
//             W1 ring 3x8192 @98304 | W2 ring 3x16384 @122880  (total 172032)
// ===========================================================================
#define MF_SMEM 172032
__global__ void __launch_bounds__(512, 1) mlp_fused_kernel(
    const float* __restrict__ x, const float* __restrict__ g2, const float* __restrict__ b2,
    const float* __restrict__ b1, const float* __restrict__ b2o, float* __restrict__ out)
{
    extern __shared__ float sm[];
    __half* Xh = (__half*)sm;                      // 32768 halves
    __half* Hh = (__half*)((char*)sm + 65536);     // 16384 halves
    float* S32  = sm + 24576;                      // LN overlay in ring region
    float* tmpS = S32 + 4160;
    float* tmpQ = tmpS + 512;
    float* mu   = tmpQ + 512;
    float* rs   = mu + 128;

    int tid = threadIdx.x, wid = tid >> 5, lane = tid & 31;
    int t0 = blockIdx.x * 128;
    uint32_t w1base = smem_u32(sm) + 98304;
    uint32_t w2base = smem_u32(sm) + 122880;

    // ---- LN2: stats + raw fp16 stash ----
    float accS = 0.f, accQ = 0.f;
    int nrole = tid & 127, part = tid >> 7;
    for (int cb = 0; cb < 8; cb++) {
        __syncthreads();
        #pragma unroll
        for (int it = 0; it < 8; it++) {
            int idx = it * 512 + tid;
            int n = idx & 127, cl = idx >> 7;
            S32[cl * 129 + n] = x[(size_t)(cb * 32 + cl) * HW + t0 + n];
        }
        __syncthreads();
        #pragma unroll
        for (int it = 0; it < 8; it++) {
            int idx = it * 512 + tid;
            int c = idx & 31, n = idx >> 5;
            S32[c * 129 + n] += g_x1[(size_t)(t0 + n) * 256 + cb * 32 + c];
        }
        __syncthreads();
        #pragma unroll
        for (int i = 0; i < 8; i++) {
            int cl = part * 8 + i;
            float v = S32[cl * 129 + nrole];
            accS += v; accQ += v * v;
            Xh[a16h(nrole, cb * 32 + cl)] = __float2half_rn(v);
        }
    }
    __syncthreads();
    tmpS[part * 128 + nrole] = accS;
    tmpQ[part * 128 + nrole] = accQ;
    __syncthreads();
    if (tid < 128) {
        float s1 = tmpS[tid] + tmpS[128 + tid] + tmpS[256 + tid] + tmpS[384 + tid];
        float s2 = tmpQ[tid] + tmpQ[128 + tid] + tmpQ[256 + tid] + tmpQ[384 + tid];
        float m = s1 * (1.f / 256.f);
        mu[tid] = m;
        rs[tid] = rsqrtf(s2 * (1.f / 256.f) - m * m + 1e-5f);
    }
    __syncthreads();
    {
        int tok = tid & 127, qr = tid >> 7;
        float m = mu[tok], r = rs[tok];
        for (int c = qr * 64; c < qr * 64 + 64; c++) {
            int hi = a16h(tok, c);
            float v = __half2float(Xh[hi]);
            Xh[hi] = __float2half_rn((v - m) * r * __ldg(g2 + c) + __ldg(b2 + c));
        }
    }
    __syncthreads();

    // ---- fused GEMM1 -> GELU -> GEMM2 over 8 hidden blocks of 128 ----
    int mwarp = wid >> 2, nwarp = wid & 3;
    int g = lane >> 2, tg = lane & 3;
    const uint4* Xu = (const uint4*)Xh;
    const uint4* Hu = (const uint4*)Hh;
    uint32_t* Hw = (uint32_t*)Hh;

    float d2[2][8][4];
    #pragma unroll
    for (int mt = 0; mt < 2; mt++)
        #pragma unroll
        for (int nt = 0; nt < 8; nt++)
            #pragma unroll
            for (int q = 0; q < 4; q++) d2[mt][nt][q] = 0.f;

    {   // prefetch W1 chunk 0 -> slot 0
        const uint4* src = (const uint4*)g_w1h;
        cp16(w1base + tid * 16, src + tid);
        CP_COMMIT();
    }

    for (int hb = 0; hb < 8; hb++) {
        float d1[2][4][4];
        #pragma unroll
        for (int mt = 0; mt < 2; mt++)
            #pragma unroll
            for (int nt = 0; nt < 4; nt++)
                #pragma unroll
                for (int q = 0; q < 4; q++) d1[mt][nt][q] = 0.f;

        // ---- GEMM1: 8 W1 chunks (k32 x n128), 3-slot ring ----
        for (int c = 0; c < 8; c++) {
            int cur = hb * 8 + c;
            if (c < 7) {
                const uint4* src = (const uint4*)g_w1h + (size_t)(cur + 1) * 512;
                uint32_t db = w1base + (uint32_t)(((cur + 1) % 3) * 8192);
                cp16(db + tid * 16, src + tid);
            } else {
                const uint4* src = (const uint4*)g_w2h + (size_t)(hb * 4) * 1024;
                uint32_t db = w2base + (uint32_t)(((hb * 4) % 3) * 16384);
                #pragma unroll
                for (int i = 0; i < 2; i++) cp16(db + (i * 512 + tid) * 16, src + i * 512 + tid);
            }
            CP_COMMIT();
            CP_WAIT1();
            __syncthreads();
            const uint2* Bu = (const uint2*)((char*)sm + 98304 + (cur % 3) * 8192);
            #pragma unroll
            for (int kb2 = 0; kb2 < 2; kb2++) {
                uint32_t a[2][4], b[4][2];
                #pragma unroll
                for (int mt = 0; mt < 2; mt++)
                    *(uint4*)a[mt] = Xu[((c * 2 + kb2) * 8 + mwarp * 2 + mt) * 32 + tg * 8 + g];
                #pragma unroll
                for (int nt = 0; nt < 4; nt++)
                    *(uint2*)b[nt] = Bu[((kb2 * 16 + nwarp * 4 + nt) * 4 + tg) * 8 + g];
                #pragma unroll
                for (int mt = 0; mt < 2; mt++)
                    #pragma unroll
                    for (int nt = 0; nt < 4; nt++)
                        mma16(d1[mt][nt], a[mt], b[nt]);
            }
        }

        // ---- GELU epilogue -> H frags in smem ----
        #pragma unroll
        for (int mt = 0; mt < 2; mt++) {
            #pragma unroll
            for (int nt = 0; nt < 4; nt++) {
                int row0 = mwarp * 32 + mt * 16 + g;
                int col0 = nwarp * 32 + nt * 8 + 2 * tg;    // local 0..127
                int cg = hb * 128 + col0;
                float b0v = b1[cg], b1v = b1[cg + 1];
                float v0 = gelu(d1[mt][nt][0] + b0v);
                float v1 = gelu(d1[mt][nt][1] + b1v);
                float v2 = gelu(d1[mt][nt][2] + b0v);
                float v3 = gelu(d1[mt][nt][3] + b1v);
                Hw[a16h(row0, col0) >> 1]     = packh2(v0, v1);
                Hw[a16h(row0 + 8, col0) >> 1] = packh2(v2, v3);
            }
        }
        __syncthreads();   // H visible before GEMM2 reads

        // ---- GEMM2: 4 W2 chunks (k32 x n256), 3-slot ring, accumulate d2 ----
        for (int c2 = 0; c2 < 4; c2++) {
            int cur2 = hb * 4 + c2;
            if (c2 < 3) {
                const uint4* src = (const uint4*)g_w2h + (size_t)(cur2 + 1) * 1024;
                uint32_t db = w2base + (uint32_t)(((cur2 + 1) % 3) * 16384);
                #pragma unroll
                for (int i = 0; i < 2; i++) cp16(db + (i * 512 + tid) * 16, src + i * 512 + tid);
            } else if (hb < 7) {
                const uint4* src = (const uint4*)g_w1h + (size_t)((hb + 1) * 8) * 512;
                uint32_t db = w1base + (uint32_t)((((hb + 1) * 8) % 3) * 8192);
                cp16(db + tid * 16, src + tid);
            }
            CP_COMMIT();
            CP_WAIT1();
            __syncthreads();
            const uint2* Bu = (const uint2*)((char*)sm + 122880 + (cur2 % 3) * 16384);
            #pragma unroll
            for (int kb2 = 0; kb2 < 2; kb2++) {
                uint32_t a[2][4], b[8][2];
                #pragma unroll
                for (int mt = 0; mt < 2; mt++)
                    *(uint4*)a[mt] = Hu[((c2 * 2 + kb2) * 8 + mwarp * 2 + mt) * 32 + tg * 8 + g];
                #pragma unroll
                for (int nt = 0; nt < 8; nt++)
                    *(uint2*)b[nt] = Bu[((kb2 * 32 + nwarp * 8 + nt) * 4 + tg) * 8 + g];
                #pragma unroll
                for (int mt = 0; mt < 2; mt++)
                    #pragma unroll
                    for (int nt = 0; nt < 8; nt++)
                        mma16(d2[mt][nt], a[mt], b[nt]);
            }
        }
        __syncthreads();   // all GEMM2 Hh reads done before next hb's GELU rewrites Hh
    }

    // ---- final epilogue: residual + NCHW store ----
    float* S = sm;        // overlay on X frags (dead now)
    for (int p = 0; p < 2; p++) {
        __syncthreads();
        #pragma unroll 4
        for (int it = 0; it < 32; it++) {
            int idx = it * 512 + tid;
            int c = idx & 255, nl = idx >> 8;
            S[c * 69 + nl] = g_x1[(size_t)(t0 + p * 64 + nl) * 256 + c];
        }
        __syncthreads();
        if ((mwarp >> 1) == p) {
            #pragma unroll
            for (int mt = 0; mt < 2; mt++) {
                #pragma unroll
                for (int nt = 0; nt < 8; nt++) {
                    int row0 = mwarp * 32 + mt * 16 + g;
                    int col0 = nwarp * 64 + nt * 8 + 2 * tg;
                    #pragma unroll
                    for (int q = 0; q < 4; q++) {
                        int col = col0 + (q & 1);
                        int row = row0 + (q >> 1) * 8;
                        float v = d2[mt][nt][q] + b2o[col]
                                + x[(size_t)col * HW + t0 + row] + S[col * 69 + (row - p * 64)];
                        out[(size_t)col * HW + t0 + row] = v;
                    }
                }
            }
        }
    }
}

// ---------------------------------------------------------------------------
extern "C" void kernel_launch(void* const* d_in, const int* in_sizes, int n_in,
                              void* d_out, int out_size) {
    const float* x        = (const float*)d_in[0];
    const float* norm1_g  = (const float*)d_in[1];
    const float* norm1_b  = (const float*)d_in[2];
    const float* qkv_r    = (const float*)d_in[3];
    const float* proj_r_w = (const float*)d_in[4];
    const float* proj_r_b = (const float*)d_in[5];
    const float* table_r  = (const float*)d_in[6];
    const float* qkv_a    = (const float*)d_in[7];
    const float* proj_a_w = (const float*)d_in[8];
    const float* proj_a_b = (const float*)d_in[9];
    const float* table_a  = (const float*)d_in[10];
    const float* norm2_g  = (const float*)d_in[11];
    const float* norm2_b  = (const float*)d_in[12];
    const float* mlp_w1   = (const float*)d_in[13];
    const float* mlp_b1   = (const float*)d_in[14];
    const float* mlp_w2   = (const float*)d_in[15];
    const float* mlp_b2   = (const float*)d_in[16];
    float* out = (float*)d_out;

    cudaFuncSetAttribute(ln1_kernel,      cudaFuncAttributeMaxDynamicSharedMemorySize, LN1_SMEM);
    cudaFuncSetAttribute(attn_kernel,     cudaFuncAttributeMaxDynamicSharedMemorySize, ATTN_SMEM);
    cudaFuncSetAttribute(mlp_fused_kernel, cudaFuncAttributeMaxDynamicSharedMemorySize, MF_SMEM);

    // order chosen so the profiler's sampled launch (#4) is attn_kernel
    ln1_kernel<<<1024, 256, LN1_SMEM>>>(x, norm1_g, norm1_b);
    wfmt2h_kernel<<<128, 256>>>(qkv_r, proj_r_w, qkv_a, proj_a_w);
    bias_kernel<<<1, 256>>>(table_r, table_a);
    attn_kernel<<<dim3(512, 2), 256, ATTN_SMEM>>>(proj_r_b, proj_a_b);
    wfmt_kernel<<<512, 256>>>(mlp_w1, mlp_w2);
    mlp_fused_kernel<<<512, 512, MF_SMEM>>>(x, norm2_g, norm2_b, mlp_b1, mlp_b2, out);
}